// round 3
// baseline (speedup 1.0000x reference)
#include <cuda_runtime.h>
#include <cuda_bf16.h>
#include <math.h>

// ---------------- problem constants ----------------
#define Bn 4
#define Qn 900
#define Kn 1024
#define En 256
#define Hn 8
#define Dn 32
#define QT 16
#define KT 32
#define SCALE_Q 0.17677669529663687f  // 1/sqrt(32)

typedef unsigned long long ull;

// ---------------- f32x2 packed helpers ----------------
__device__ __forceinline__ ull pk2(float lo, float hi) {
    ull r; asm("mov.b64 %0, {%1,%2};" : "=l"(r) : "f"(lo), "f"(hi)); return r;
}
__device__ __forceinline__ void upk2(ull v, float& lo, float& hi) {
    asm("mov.b64 {%0,%1}, %2;" : "=f"(lo), "=f"(hi) : "l"(v));
}
__device__ __forceinline__ ull fma2(ull a, ull b, ull c) {
    ull r; asm("fma.rn.f32x2 %0, %1, %2, %3;" : "=l"(r) : "l"(a), "l"(b), "l"(c)); return r;
}
__device__ __forceinline__ ull mul2(ull a, ull b) {
    ull r; asm("mul.rn.f32x2 %0, %1, %2;" : "=l"(r) : "l"(a), "l"(b)); return r;
}
__device__ __forceinline__ ull add2(ull a, ull b) {
    ull r; asm("add.rn.f32x2 %0, %1, %2;" : "=l"(r) : "l"(a), "l"(b)); return r;
}

// ---------------- scratch ----------------
__device__ __align__(16) float g_q[Bn * Qn * En];
__device__ __align__(16) float g_k[Bn * Kn * En];
__device__ __align__(16) float g_v[Bn * Kn * En];
__device__ __align__(16) float g_att[Bn * Qn * En];

// ---------------- projection GEMM (f32x2 inner) ----------------
__global__ __launch_bounds__(256) void proj_gemm(
    const float* __restrict__ A, const float* __restrict__ W,
    const float* __restrict__ bias, float* __restrict__ C,
    int M, float scale)
{
    __shared__ __align__(16) float As[16][64];
    __shared__ __align__(16) float Bs[16][64];

    const int m0 = blockIdx.x * 64;
    const int n0 = blockIdx.y * 64;
    const int t  = threadIdx.x;
    const int tx = t & 15;
    const int ty = t >> 4;
    const int lr = t >> 2;
    const int lc = (t & 3) * 4;

    ull acc2[4][2];
#pragma unroll
    for (int i = 0; i < 4; i++) { acc2[i][0] = 0ULL; acc2[i][1] = 0ULL; }

    for (int k0 = 0; k0 < 256; k0 += 16) {
        float4 a4 = make_float4(0.f, 0.f, 0.f, 0.f);
        if (m0 + lr < M)
            a4 = *(const float4*)&A[(size_t)(m0 + lr) * 256 + k0 + lc];
        As[lc + 0][lr] = a4.x; As[lc + 1][lr] = a4.y;
        As[lc + 2][lr] = a4.z; As[lc + 3][lr] = a4.w;

        float4 b4 = *(const float4*)&W[(size_t)(n0 + lr) * 256 + k0 + lc];
        Bs[lc + 0][lr] = b4.x; Bs[lc + 1][lr] = b4.y;
        Bs[lc + 2][lr] = b4.z; Bs[lc + 3][lr] = b4.w;
        __syncthreads();

#pragma unroll
        for (int kk = 0; kk < 16; kk++) {
            float4 av = *(const float4*)&As[kk][ty * 4];
            float4 bv = *(const float4*)&Bs[kk][tx * 4];
            ull b01 = pk2(bv.x, bv.y);
            ull b23 = pk2(bv.z, bv.w);
            float am[4] = {av.x, av.y, av.z, av.w};
#pragma unroll
            for (int i = 0; i < 4; i++) {
                ull ad = pk2(am[i], am[i]);
                acc2[i][0] = fma2(b01, ad, acc2[i][0]);
                acc2[i][1] = fma2(b23, ad, acc2[i][1]);
            }
        }
        __syncthreads();
    }

#pragma unroll
    for (int i = 0; i < 4; i++) {
        int m = m0 + ty * 4 + i;
        if (m < M) {
            int n = n0 + tx * 4;
            float c0, c1, c2, c3;
            upk2(acc2[i][0], c0, c1);
            upk2(acc2[i][1], c2, c3);
            float4 o;
            o.x = scale * (c0 + bias[n + 0]);
            o.y = scale * (c1 + bias[n + 1]);
            o.z = scale * (c2 + bias[n + 2]);
            o.w = scale * (c3 + bias[n + 3]);
            *(float4*)&C[(size_t)m * 256 + n] = o;
        }
    }
}

// ---------------- fused attention ----------------
// SMEM (float offsets):
#define SM_Q    0        // [16][260]  4160
#define SM_K    4160     // [32][260]  8320
#define SM_V    12480    // [32][260]  8320
#define SM_P    20800    // [16][8][34] 4352   (cpb written by B1, exp'd in place by B2)
#define SM_W1   25152    // float4[64] (wx,wx,wy,wy)  256
#define SM_BD   25408    // ull[64] (b,b)             128
#define SM_W2   25536    // ull[64][4] head-pairs     512
#define SM_B2   26048    // ull[4] bc2 pairs            8
#define SM_FLOATS 26056
#define SM_BYTES (SM_FLOATS * 4)
#define MASK_NEG (-10000.0f)

__global__ __launch_bounds__(256, 2) void attn_kernel(
    const float* __restrict__ rd, const unsigned char* __restrict__ mask,
    const float* __restrict__ Wc1, const float* __restrict__ bc1,
    const float* __restrict__ Wc2, const float* __restrict__ bc2)
{
    extern __shared__ __align__(16) float sm[];
    float*  q_s = sm + SM_Q;
    float*  k_s = sm + SM_K;
    float*  v_s = sm + SM_V;
    float*  p_s = sm + SM_P;
    float4* w1d = (float4*)(sm + SM_W1);
    ull*    bd  = (ull*)(sm + SM_BD);
    ull*    w2p = (ull*)(sm + SM_W2);
    ull*    b2p = (ull*)(sm + SM_B2);

    const int b  = blockIdx.y;
    const int q0 = blockIdx.x * QT;
    const int t  = threadIdx.x;

    // ---- prologue: q tile + CPB weights ----
#pragma unroll
    for (int i = 0; i < 4; i++) {
        int idx = t + i * 256;            // 1024 float4 = 16 rows x 64 chunks
        int qq  = idx >> 6, e4 = idx & 63;
        float4 val = make_float4(0.f, 0.f, 0.f, 0.f);
        if (q0 + qq < Qn)
            val = *(const float4*)&g_q[(size_t)((b * Qn) + (q0 + qq)) * En + e4 * 4];
        *(float4*)&q_s[qq * 260 + e4 * 4] = val;
    }
    if (t < 64) {
        float wx = Wc1[2 * t], wy = Wc1[2 * t + 1];
        w1d[t] = make_float4(wx, wx, wy, wy);
        bd[t]  = pk2(bc1[t], bc1[t]);
#pragma unroll
        for (int hp = 0; hp < 4; hp++)
            w2p[t * 4 + hp] = pk2(Wc2[(2 * hp) * 64 + t], Wc2[(2 * hp + 1) * 64 + t]);
    }
    if (t < 4) b2p[t] = pk2(bc2[2 * t], bc2[2 * t + 1]);
    __syncthreads();

    // phase identities
    const int bq  = t >> 4;           // B1: query 0..15
    const int bk2 = (t & 15) * 2;     // B1: key pair base
    const int wh  = t >> 5;           // B2: head (warp)
    const int wk  = t & 31;           // B2: key lane
    const int cq  = t >> 4;           // C : query
    const int eg  = t & 15;           // C : 16-dim group
    const int ch  = eg >> 1;          // C : head

    float l_run = 0.f;
    ull o[8];
#pragma unroll
    for (int d = 0; d < 8; d++) o[d] = 0ULL;

    for (int k0 = 0; k0 < Kn; k0 += KT) {
        // ---- early loads for B1 (overlap with phase A) ----
        int qg1 = q0 + bq;
        float4 r4 = make_float4(0.f, 0.f, 0.f, 0.f);
        if (qg1 < Qn)
            r4 = *(const float4*)&rd[(((size_t)b * Qn + qg1) * Kn + (k0 + bk2)) * 2];
        uchar2 mm = *(const uchar2*)&mask[b * Kn + k0 + bk2];

        // ===== Phase A: load K/V tile =====
#pragma unroll
        for (int i = 0; i < 8; i++) {
            int idx = t + i * 256;
            int kk  = idx >> 6, e4 = idx & 63;
            size_t gidx = (size_t)((b * Kn) + (k0 + kk)) * En + e4 * 4;
            *(float4*)&k_s[kk * 260 + e4 * 4] = *(const float4*)&g_k[gidx];
            *(float4*)&v_s[kk * 260 + e4 * 4] = *(const float4*)&g_v[gidx];
        }

        // ===== Phase B1: CPB MLP, packed over 2 keys =====
        {
            ull dx2 = pk2(r4.x, r4.z);
            ull dy2 = pk2(r4.y, r4.w);
            ull a00 = b2p[0], a01 = b2p[1], a02 = b2p[2], a03 = b2p[3]; // k0: head pairs
            ull a10 = b2p[0], a11 = b2p[1], a12 = b2p[2], a13 = b2p[3]; // k1
#pragma unroll 16
            for (int j = 0; j < 64; j++) {
                float4 w = w1d[j];
                ull h2 = fma2(pk2(w.x, w.y), dx2, fma2(pk2(w.z, w.w), dy2, bd[j]));
                float h0, h1; upk2(h2, h0, h1);
                h0 = fmaxf(h0, 0.f);
                h1 = fmaxf(h1, 0.f);
                ull h0d = pk2(h0, h0);
                ull h1d = pk2(h1, h1);
                ulonglong2 wa = *(const ulonglong2*)&w2p[j * 4];
                ulonglong2 wb = *(const ulonglong2*)&w2p[j * 4 + 2];
                a00 = fma2(wa.x, h0d, a00);
                a01 = fma2(wa.y, h0d, a01);
                a02 = fma2(wb.x, h0d, a02);
                a03 = fma2(wb.y, h0d, a03);
                a10 = fma2(wa.x, h1d, a10);
                a11 = fma2(wa.y, h1d, a11);
                a12 = fma2(wb.x, h1d, a12);
                a13 = fma2(wb.y, h1d, a13);
            }
            ull mb = pk2(mm.x ? MASK_NEG : 0.f, mm.y ? MASK_NEG : 0.f);
            int base = bq * 8 * 34 + bk2;
            float e0, e1, f0, f1;
            upk2(a00, e0, e1); upk2(a10, f0, f1);
            *(ull*)&p_s[base + 0 * 34] = add2(pk2(e0, f0), mb);
            *(ull*)&p_s[base + 1 * 34] = add2(pk2(e1, f1), mb);
            upk2(a01, e0, e1); upk2(a11, f0, f1);
            *(ull*)&p_s[base + 2 * 34] = add2(pk2(e0, f0), mb);
            *(ull*)&p_s[base + 3 * 34] = add2(pk2(e1, f1), mb);
            upk2(a02, e0, e1); upk2(a12, f0, f1);
            *(ull*)&p_s[base + 4 * 34] = add2(pk2(e0, f0), mb);
            *(ull*)&p_s[base + 5 * 34] = add2(pk2(e1, f1), mb);
            upk2(a03, e0, e1); upk2(a13, f0, f1);
            *(ull*)&p_s[base + 6 * 34] = add2(pk2(e0, f0), mb);
            *(ull*)&p_s[base + 7 * 34] = add2(pk2(e1, f1), mb);
        }
        __syncthreads();

        // ===== Phase B2: QK dot + exp (no max subtraction; scores bounded) =====
        {
            ull kf[16];
#pragma unroll
            for (int i = 0; i < 8; i++) {
                float4 v4 = *(const float4*)&k_s[wk * 260 + wh * 32 + i * 4];
                kf[2 * i]     = pk2(v4.x, v4.y);
                kf[2 * i + 1] = pk2(v4.z, v4.w);
            }
#pragma unroll
            for (int q = 0; q < 16; q++) {
                const float* qr = &q_s[q * 260 + wh * 32];
                float4 q4 = *(const float4*)&qr[0];
                ull d2 = mul2(pk2(q4.x, q4.y), kf[0]);
                d2 = fma2(pk2(q4.z, q4.w), kf[1], d2);
#pragma unroll
                for (int i = 1; i < 8; i++) {
                    float4 qv = *(const float4*)&qr[i * 4];
                    d2 = fma2(pk2(qv.x, qv.y), kf[2 * i], d2);
                    d2 = fma2(pk2(qv.z, qv.w), kf[2 * i + 1], d2);
                }
                float lo, hi; upk2(d2, lo, hi);
                int ad = (q * 8 + wh) * 34 + wk;
                float p = __expf(lo + hi + p_s[ad]);
                p_s[ad] = p;
            }
        }
        __syncthreads();

        // ===== Phase C: AV accumulate =====
        {
            const float* pr = &p_s[(cq * 8 + ch) * 34];
            const float* vb = &v_s[eg * 16];
#pragma unroll 8
            for (int kl = 0; kl < KT; kl++) {
                float p = pr[kl];
                ull pd = pk2(p, p);
                l_run += p;
                float4 va = *(const float4*)&vb[kl * 260];
                float4 v2 = *(const float4*)&vb[kl * 260 + 4];
                float4 v3 = *(const float4*)&vb[kl * 260 + 8];
                float4 v4 = *(const float4*)&vb[kl * 260 + 12];
                o[0] = fma2(pk2(va.x, va.y), pd, o[0]);
                o[1] = fma2(pk2(va.z, va.w), pd, o[1]);
                o[2] = fma2(pk2(v2.x, v2.y), pd, o[2]);
                o[3] = fma2(pk2(v2.z, v2.w), pd, o[3]);
                o[4] = fma2(pk2(v3.x, v3.y), pd, o[4]);
                o[5] = fma2(pk2(v3.z, v3.w), pd, o[5]);
                o[6] = fma2(pk2(v4.x, v4.y), pd, o[6]);
                o[7] = fma2(pk2(v4.z, v4.w), pd, o[7]);
            }
        }
        __syncthreads();
    }

    // ---- epilogue ----
    int qg = q0 + cq;
    if (qg < Qn) {
        float inv = 1.f / l_run;
        ull invd = pk2(inv, inv);
        float* dst = &g_att[(size_t)((b * Qn) + qg) * En + eg * 16];
#pragma unroll
        for (int i = 0; i < 4; i++) {
            ull u0 = mul2(o[2 * i], invd);
            ull u1 = mul2(o[2 * i + 1], invd);
            float a, bb, c, d;
            upk2(u0, a, bb);
            upk2(u1, c, d);
            *(float4*)&dst[i * 4] = make_float4(a, bb, c, d);
        }
    }
}

// ---------------- launch ----------------
extern "C" void kernel_launch(void* const* d_in, const int* in_sizes, int n_in,
                              void* d_out, int out_size)
{
    const float*         nodes  = (const float*)d_in[0];
    const float*         images = (const float*)d_in[1];
    const unsigned char* imask  = (const unsigned char*)d_in[2];
    const float*         rd     = (const float*)d_in[3];
    const float*         Wq     = (const float*)d_in[4];
    const float*         bq     = (const float*)d_in[5];
    const float*         Wkv    = (const float*)d_in[6];
    const float*         bkv    = (const float*)d_in[7];
    const float*         Wc1    = (const float*)d_in[8];
    const float*         bc1    = (const float*)d_in[9];
    const float*         Wc2    = (const float*)d_in[10];
    const float*         bc2    = (const float*)d_in[11];
    const float*         Wo     = (const float*)d_in[12];
    const float*         bo     = (const float*)d_in[13];
    float*               out    = (float*)d_out;

    float *pq, *pk, *pv, *pa;
    cudaGetSymbolAddress((void**)&pq, g_q);
    cudaGetSymbolAddress((void**)&pk, g_k);
    cudaGetSymbolAddress((void**)&pv, g_v);
    cudaGetSymbolAddress((void**)&pa, g_att);

    const int MQ = Bn * Qn;   // 3600
    const int MK = Bn * Kn;   // 4096

    {
        dim3 g((MQ + 63) / 64, 4);
        proj_gemm<<<g, 256>>>(nodes, Wq, bq, pq, MQ, SCALE_Q);
    }
    {
        dim3 g((MK + 63) / 64, 4);
        proj_gemm<<<g, 256>>>(images, Wkv,             bkv,       pk, MK, 1.f);
        proj_gemm<<<g, 256>>>(images, Wkv + 256 * 256, bkv + 256, pv, MK, 1.f);
    }
    {
        cudaFuncSetAttribute(attn_kernel,
                             cudaFuncAttributeMaxDynamicSharedMemorySize, SM_BYTES);
        dim3 g((Qn + QT - 1) / QT, Bn);   // (57, 4) = 228 CTAs -> single wave
        attn_kernel<<<g, 256, SM_BYTES>>>(rd, imask, Wc1, bc1, Wc2, bc2);
    }
    {
        dim3 g((MQ + 63) / 64, 4);
        proj_gemm<<<g, 256>>>(pa, Wo, bo, out, MQ, 1.f);
    }
}

// round 4
// speedup vs baseline: 1.4387x; 1.4387x over previous
#include <cuda_runtime.h>
#include <cuda_bf16.h>
#include <math.h>

// ---------------- problem constants ----------------
#define Bn 4
#define Qn 900
#define Kn 1024
#define En 256
#define Hn 8
#define Dn 32
#define QT 8
#define KT 32
#define NTILES (Kn / KT)
#define SCALE_Q 0.17677669529663687f  // 1/sqrt(32)
#define MASK_NEG (-10000.0f)

typedef unsigned long long ull;

// ---------------- f32x2 packed helpers ----------------
__device__ __forceinline__ ull pk2(float lo, float hi) {
    ull r; asm("mov.b64 %0, {%1,%2};" : "=l"(r) : "f"(lo), "f"(hi)); return r;
}
__device__ __forceinline__ void upk2(ull v, float& lo, float& hi) {
    asm("mov.b64 {%0,%1}, %2;" : "=f"(lo), "=f"(hi) : "l"(v));
}
__device__ __forceinline__ ull fma2(ull a, ull b, ull c) {
    ull r; asm("fma.rn.f32x2 %0, %1, %2, %3;" : "=l"(r) : "l"(a), "l"(b), "l"(c)); return r;
}

// ---------------- cp.async helpers ----------------
__device__ __forceinline__ void cpa16(unsigned int dst, const void* src) {
    asm volatile("cp.async.cg.shared.global [%0], [%1], 16;" :: "r"(dst), "l"(src));
}
#define CP_COMMIT() asm volatile("cp.async.commit_group;")
#define CP_WAIT0()  asm volatile("cp.async.wait_group 0;" ::: "memory")

// ---------------- scratch ----------------
__device__ __align__(16) float g_q[Bn * Qn * En];
__device__ __align__(16) float g_k[Bn * Kn * En];
__device__ __align__(16) float g_v[Bn * Kn * En];
__device__ __align__(16) float g_att[Bn * Qn * En];

// ---------------- projection GEMM ----------------
__global__ __launch_bounds__(256) void proj_gemm(
    const float* __restrict__ A, const float* __restrict__ W,
    const float* __restrict__ bias, float* __restrict__ C,
    int M, float scale)
{
    __shared__ __align__(16) float As[16][64];
    __shared__ __align__(16) float Bs[16][64];

    const int m0 = blockIdx.x * 64;
    const int n0 = blockIdx.y * 64;
    const int t  = threadIdx.x;
    const int tx = t & 15;
    const int ty = t >> 4;
    const int lr = t >> 2;
    const int lc = (t & 3) * 4;

    ull acc2[4][2];
#pragma unroll
    for (int i = 0; i < 4; i++) { acc2[i][0] = 0ULL; acc2[i][1] = 0ULL; }

    for (int k0 = 0; k0 < 256; k0 += 16) {
        float4 a4 = make_float4(0.f, 0.f, 0.f, 0.f);
        if (m0 + lr < M)
            a4 = *(const float4*)&A[(size_t)(m0 + lr) * 256 + k0 + lc];
        As[lc + 0][lr] = a4.x; As[lc + 1][lr] = a4.y;
        As[lc + 2][lr] = a4.z; As[lc + 3][lr] = a4.w;

        float4 b4 = *(const float4*)&W[(size_t)(n0 + lr) * 256 + k0 + lc];
        Bs[lc + 0][lr] = b4.x; Bs[lc + 1][lr] = b4.y;
        Bs[lc + 2][lr] = b4.z; Bs[lc + 3][lr] = b4.w;
        __syncthreads();

#pragma unroll
        for (int kk = 0; kk < 16; kk++) {
            float4 av = *(const float4*)&As[kk][ty * 4];
            float4 bv = *(const float4*)&Bs[kk][tx * 4];
            ull b01 = pk2(bv.x, bv.y);
            ull b23 = pk2(bv.z, bv.w);
            float am[4] = {av.x, av.y, av.z, av.w};
#pragma unroll
            for (int i = 0; i < 4; i++) {
                ull ad = pk2(am[i], am[i]);
                acc2[i][0] = fma2(b01, ad, acc2[i][0]);
                acc2[i][1] = fma2(b23, ad, acc2[i][1]);
            }
        }
        __syncthreads();
    }

#pragma unroll
    for (int i = 0; i < 4; i++) {
        int m = m0 + ty * 4 + i;
        if (m < M) {
            int n = n0 + tx * 4;
            float c0, c1, c2, c3;
            upk2(acc2[i][0], c0, c1);
            upk2(acc2[i][1], c2, c3);
            float4 o;
            o.x = scale * (c0 + bias[n + 0]);
            o.y = scale * (c1 + bias[n + 1]);
            o.z = scale * (c2 + bias[n + 2]);
            o.w = scale * (c3 + bias[n + 3]);
            *(float4*)&C[(size_t)m * 256 + n] = o;
        }
    }
}

// ---------------- fused attention ----------------
// SMEM (float offsets)
#define SM_Q     0        // [8][260]    2080
#define SM_K     2080     // [32][260]   8320
#define SM_V     10400    // [32][260]   8320
#define SM_P     18720    // [8][8][33]  2112
#define SM_CPB0  20832    // [8][8][33]  2112
#define SM_CPB1  22944    // [8][8][33]  2112
#define SM_W1    25056    // float4[64]  (wx,wy,b,0)  256
#define SM_W2    25312    // ull[64][4]  head pairs   512
#define SM_B2    25824    // ull[4]                     8
#define SM_FLOATS 25832
#define SM_BYTES (SM_FLOATS * 4)

// CPB MLP for one (q,k) pair across all 8 heads, packed over head pairs.
__device__ __forceinline__ void cpb_compute(
    float* __restrict__ dst, const float4* __restrict__ w1,
    const ull* __restrict__ w2p, const ull* __restrict__ b2p,
    float dx, float dy, bool masked, int bq, int bk)
{
    ull a0 = b2p[0], a1 = b2p[1], a2 = b2p[2], a3 = b2p[3];
#pragma unroll 16
    for (int j = 0; j < 64; j++) {
        float4 w = w1[j];
        float hj = fmaxf(fmaf(w.x, dx, fmaf(w.y, dy, w.z)), 0.f);
        ull hd = pk2(hj, hj);
        ulonglong2 wa = *(const ulonglong2*)&w2p[j * 4];
        ulonglong2 wb = *(const ulonglong2*)&w2p[j * 4 + 2];
        a0 = fma2(wa.x, hd, a0);
        a1 = fma2(wa.y, hd, a1);
        a2 = fma2(wb.x, hd, a2);
        a3 = fma2(wb.y, hd, a3);
    }
    float m = masked ? MASK_NEG : 0.f;
    float e0, e1;
    float* base = dst + bq * 8 * 33 + bk;
    upk2(a0, e0, e1); base[0 * 33] = e0 + m; base[1 * 33] = e1 + m;
    upk2(a1, e0, e1); base[2 * 33] = e0 + m; base[3 * 33] = e1 + m;
    upk2(a2, e0, e1); base[4 * 33] = e0 + m; base[5 * 33] = e1 + m;
    upk2(a3, e0, e1); base[6 * 33] = e0 + m; base[7 * 33] = e1 + m;
}

__global__ __launch_bounds__(256, 2) void attn_kernel(
    const float* __restrict__ rd, const unsigned char* __restrict__ mask,
    const float* __restrict__ Wc1, const float* __restrict__ bc1,
    const float* __restrict__ Wc2, const float* __restrict__ bc2)
{
    extern __shared__ __align__(16) float sm[];
    float*  q_s = sm + SM_Q;
    float*  k_s = sm + SM_K;
    float*  v_s = sm + SM_V;
    float*  p_s = sm + SM_P;
    float4* w1  = (float4*)(sm + SM_W1);
    ull*    w2p = (ull*)(sm + SM_W2);
    ull*    b2p = (ull*)(sm + SM_B2);

    const int b  = blockIdx.y;
    const int q0 = blockIdx.x * QT;
    const int t  = threadIdx.x;
    const unsigned int smem_u32 = (unsigned int)__cvta_generic_to_shared(sm);

    // ---- prologue: q tile + weights ----
#pragma unroll
    for (int i = 0; i < 2; i++) {
        int idx = t + i * 256;            // 512 float4 = 8 rows x 64 chunks
        int qq  = idx >> 6, e4 = idx & 63;
        float4 val = make_float4(0.f, 0.f, 0.f, 0.f);
        if (q0 + qq < Qn)
            val = *(const float4*)&g_q[(size_t)((b * Qn) + (q0 + qq)) * En + e4 * 4];
        *(float4*)&q_s[qq * 260 + e4 * 4] = val;
    }
    if (t < 64) {
        w1[t] = make_float4(Wc1[2 * t], Wc1[2 * t + 1], bc1[t], 0.f);
#pragma unroll
        for (int hp = 0; hp < 4; hp++)
            w2p[t * 4 + hp] = pk2(Wc2[(2 * hp) * 64 + t], Wc2[(2 * hp + 1) * 64 + t]);
    }
    if (t < 4) b2p[t] = pk2(bc2[2 * t], bc2[2 * t + 1]);
    __syncthreads();

    // thread identities
    const int bq = t >> 5;        // B1 query / B2 warp head
    const int bk = t & 31;        // B1 key lane / B2 key lane
    const int wh = bq;            // head owned by this warp (B2 & C)
    const int cq = bk >> 2;       // C: query
    const int dg = bk & 3;        // C: 8-dim group within head

    const int qg_b1 = q0 + bq;
    const size_t rd_row = ((size_t)b * Qn + (qg_b1 < Qn ? qg_b1 : Qn - 1)) * Kn;

    // ---- tile 0: async K/V load + CPB compute (overlapped) ----
    {
#pragma unroll
        for (int i = 0; i < 8; i++) {
            int idx = t + i * 256;
            int kk  = idx >> 6, e4 = idx & 63;
            size_t gidx = (size_t)((b * Kn) + kk) * En + e4 * 4;
            unsigned int off = (kk * 260 + e4 * 4) * 4;
            cpa16(smem_u32 + SM_K * 4 + off, &g_k[gidx]);
            cpa16(smem_u32 + SM_V * 4 + off, &g_v[gidx]);
        }
        CP_COMMIT();
        float2 r2 = *(const float2*)&rd[(rd_row + bk) * 2];
        bool mk = mask[b * Kn + bk] != 0;
        cpb_compute(sm + SM_CPB0, w1, w2p, b2p, r2.x, r2.y, mk, bq, bk);
        CP_WAIT0();
        __syncthreads();
    }

    float l_run = 0.f;
    float o[8];
#pragma unroll
    for (int d = 0; d < 8; d++) o[d] = 0.f;

    for (int it = 0; it < NTILES; it++) {
        const int k0 = it * KT;
        float* cpb_cur = sm + ((it & 1) ? SM_CPB1 : SM_CPB0);
        float* cpb_nxt = sm + ((it & 1) ? SM_CPB0 : SM_CPB1);

        // prefetch rd/mask for next tile (LDG in flight during B2+C)
        float2 r2 = make_float2(0.f, 0.f);
        bool mk = false;
        if (it + 1 < NTILES) {
            r2 = *(const float2*)&rd[(rd_row + k0 + KT + bk) * 2];
            mk = mask[b * Kn + k0 + KT + bk] != 0;
        }

        // ===== B2: QK dot + exp for head wh (warp-local) =====
        {
            float kf[32];
#pragma unroll
            for (int i = 0; i < 8; i++) {
                float4 v4 = *(const float4*)&k_s[bk * 260 + wh * 32 + i * 4];
                kf[4 * i + 0] = v4.x; kf[4 * i + 1] = v4.y;
                kf[4 * i + 2] = v4.z; kf[4 * i + 3] = v4.w;
            }
            float pv[8];
#pragma unroll
            for (int q = 0; q < 8; q++) {
                const float* qr = &q_s[q * 260 + wh * 32];
                float dot = 0.f;
#pragma unroll
                for (int i = 0; i < 8; i++) {
                    float4 qv = *(const float4*)&qr[i * 4];
                    dot = fmaf(qv.x, kf[4 * i + 0], dot);
                    dot = fmaf(qv.y, kf[4 * i + 1], dot);
                    dot = fmaf(qv.z, kf[4 * i + 2], dot);
                    dot = fmaf(qv.w, kf[4 * i + 3], dot);
                }
                pv[q] = __expf(dot + cpb_cur[(q * 8 + wh) * 33 + bk]);
            }
#pragma unroll
            for (int q = 0; q < 8; q++)
                p_s[(q * 8 + wh) * 33 + bk] = pv[q];
        }
        __syncwarp();

        // ===== C: AV accumulate for head wh (warp-local) =====
        {
            const float* pr = &p_s[(cq * 8 + wh) * 33];
            const float* vb = &v_s[wh * 32 + dg * 8];
#pragma unroll 8
            for (int kl = 0; kl < KT; kl++) {
                float p = pr[kl];
                l_run += p;
                float4 va = *(const float4*)&vb[kl * 260];
                float4 v2 = *(const float4*)&vb[kl * 260 + 4];
                o[0] = fmaf(p, va.x, o[0]);
                o[1] = fmaf(p, va.y, o[1]);
                o[2] = fmaf(p, va.z, o[2]);
                o[3] = fmaf(p, va.w, o[3]);
                o[4] = fmaf(p, v2.x, o[4]);
                o[5] = fmaf(p, v2.y, o[5]);
                o[6] = fmaf(p, v2.z, o[6]);
                o[7] = fmaf(p, v2.w, o[7]);
            }
        }

        // ===== prefetch next K/V tile + next CPB (overlapped) =====
        if (it + 1 < NTILES) {
            __syncthreads();      // everyone done reading k_s/v_s/p_s of tile it
#pragma unroll
            for (int i = 0; i < 8; i++) {
                int idx = t + i * 256;
                int kk  = idx >> 6, e4 = idx & 63;
                size_t gidx = (size_t)((b * Kn) + (k0 + KT + kk)) * En + e4 * 4;
                unsigned int off = (kk * 260 + e4 * 4) * 4;
                cpa16(smem_u32 + SM_K * 4 + off, &g_k[gidx]);
                cpa16(smem_u32 + SM_V * 4 + off, &g_v[gidx]);
            }
            CP_COMMIT();
            cpb_compute(cpb_nxt, w1, w2p, b2p, r2.x, r2.y, mk, bq, bk);
            CP_WAIT0();
            __syncthreads();      // k_s/v_s + cpb_nxt visible to all warps
        }
    }

    // ---- epilogue: lane (cq, dg) owns dims [wh*32 + dg*8, +8) of query cq ----
    int qg = q0 + cq;
    if (qg < Qn) {
        float inv = 1.f / l_run;
        float* dst = &g_att[(size_t)((b * Qn) + qg) * En + wh * 32 + dg * 8];
        *(float4*)&dst[0] = make_float4(o[0] * inv, o[1] * inv, o[2] * inv, o[3] * inv);
        *(float4*)&dst[4] = make_float4(o[4] * inv, o[5] * inv, o[6] * inv, o[7] * inv);
    }
}

// ---------------- launch ----------------
extern "C" void kernel_launch(void* const* d_in, const int* in_sizes, int n_in,
                              void* d_out, int out_size)
{
    const float*         nodes  = (const float*)d_in[0];
    const float*         images = (const float*)d_in[1];
    const unsigned char* imask  = (const unsigned char*)d_in[2];
    const float*         rd     = (const float*)d_in[3];
    const float*         Wq     = (const float*)d_in[4];
    const float*         bq     = (const float*)d_in[5];
    const float*         Wkv    = (const float*)d_in[6];
    const float*         bkv    = (const float*)d_in[7];
    const float*         Wc1    = (const float*)d_in[8];
    const float*         bc1    = (const float*)d_in[9];
    const float*         Wc2    = (const float*)d_in[10];
    const float*         bc2    = (const float*)d_in[11];
    const float*         Wo     = (const float*)d_in[12];
    const float*         bo     = (const float*)d_in[13];
    float*               out    = (float*)d_out;

    float *pq, *pk, *pv, *pa;
    cudaGetSymbolAddress((void**)&pq, g_q);
    cudaGetSymbolAddress((void**)&pk, g_k);
    cudaGetSymbolAddress((void**)&pv, g_v);
    cudaGetSymbolAddress((void**)&pa, g_att);

    const int MQ = Bn * Qn;   // 3600
    const int MK = Bn * Kn;   // 4096

    {
        dim3 g((MQ + 63) / 64, 4);
        proj_gemm<<<g, 256>>>(nodes, Wq, bq, pq, MQ, SCALE_Q);
    }
    {
        dim3 g((MK + 63) / 64, 4);
        proj_gemm<<<g, 256>>>(images, Wkv,             bkv,       pk, MK, 1.f);
        proj_gemm<<<g, 256>>>(images, Wkv + 256 * 256, bkv + 256, pv, MK, 1.f);
    }
    {
        cudaFuncSetAttribute(attn_kernel,
                             cudaFuncAttributeMaxDynamicSharedMemorySize, SM_BYTES);
        dim3 g((Qn + QT - 1) / QT, Bn);   // (113, 4) = 452 CTAs
        attn_kernel<<<g, 256, SM_BYTES>>>(rd, imask, Wc1, bc1, Wc2, bc2);
    }
    {
        dim3 g((MQ + 63) / 64, 4);
        proj_gemm<<<g, 256>>>(pa, Wo, bo, out, MQ, 1.f);
    }
}

// round 5
// speedup vs baseline: 1.4541x; 1.0107x over previous
#include <cuda_runtime.h>
#include <cuda_bf16.h>
#include <math.h>

// ---------------- problem constants ----------------
#define Bn 4
#define Qn 900
#define Kn 1024
#define En 256
#define Hn 8
#define Dn 32
#define QT 8
#define KT 32
#define NTILES (Kn / KT)
#define SCALE_Q 0.17677669529663687f  // 1/sqrt(32)
#define MASK_NEG (-10000.0f)

typedef unsigned long long ull;

// ---------------- f32x2 packed helpers ----------------
__device__ __forceinline__ ull pk2(float lo, float hi) {
    ull r; asm("mov.b64 %0, {%1,%2};" : "=l"(r) : "f"(lo), "f"(hi)); return r;
}
__device__ __forceinline__ void upk2(ull v, float& lo, float& hi) {
    asm("mov.b64 {%0,%1}, %2;" : "=f"(lo), "=f"(hi) : "l"(v));
}
__device__ __forceinline__ ull fma2(ull a, ull b, ull c) {
    ull r; asm("fma.rn.f32x2 %0, %1, %2, %3;" : "=l"(r) : "l"(a), "l"(b), "l"(c)); return r;
}
__device__ __forceinline__ ull mul2(ull a, ull b) {
    ull r; asm("mul.rn.f32x2 %0, %1, %2;" : "=l"(r) : "l"(a), "l"(b)); return r;
}

// ---------------- cp.async helpers ----------------
__device__ __forceinline__ void cpa16(unsigned int dst, const void* src) {
    asm volatile("cp.async.cg.shared.global [%0], [%1], 16;" :: "r"(dst), "l"(src));
}
#define CP_COMMIT() asm volatile("cp.async.commit_group;")
#define CP_WAIT0()  asm volatile("cp.async.wait_group 0;" ::: "memory")
#define CP_WAIT1()  asm volatile("cp.async.wait_group 1;" ::: "memory")

// ---------------- scratch ----------------
__device__ __align__(16) float g_q[Bn * Qn * En];
__device__ __align__(16) float g_k[Bn * Kn * En];
__device__ __align__(16) float g_v[Bn * Kn * En];
__device__ __align__(16) float g_att[Bn * Qn * En];

// ---------------- projection GEMM ----------------
__global__ __launch_bounds__(256) void proj_gemm(
    const float* __restrict__ A, const float* __restrict__ W,
    const float* __restrict__ bias, float* __restrict__ C,
    int M, float scale)
{
    __shared__ __align__(16) float As[16][64];
    __shared__ __align__(16) float Bs[16][64];

    const int m0 = blockIdx.x * 64;
    const int n0 = blockIdx.y * 64;
    const int t  = threadIdx.x;
    const int tx = t & 15;
    const int ty = t >> 4;
    const int lr = t >> 2;
    const int lc = (t & 3) * 4;

    ull acc2[4][2];
#pragma unroll
    for (int i = 0; i < 4; i++) { acc2[i][0] = 0ULL; acc2[i][1] = 0ULL; }

    for (int k0 = 0; k0 < 256; k0 += 16) {
        float4 a4 = make_float4(0.f, 0.f, 0.f, 0.f);
        if (m0 + lr < M)
            a4 = *(const float4*)&A[(size_t)(m0 + lr) * 256 + k0 + lc];
        As[lc + 0][lr] = a4.x; As[lc + 1][lr] = a4.y;
        As[lc + 2][lr] = a4.z; As[lc + 3][lr] = a4.w;

        float4 b4 = *(const float4*)&W[(size_t)(n0 + lr) * 256 + k0 + lc];
        Bs[lc + 0][lr] = b4.x; Bs[lc + 1][lr] = b4.y;
        Bs[lc + 2][lr] = b4.z; Bs[lc + 3][lr] = b4.w;
        __syncthreads();

#pragma unroll
        for (int kk = 0; kk < 16; kk++) {
            float4 av = *(const float4*)&As[kk][ty * 4];
            float4 bv = *(const float4*)&Bs[kk][tx * 4];
            ull b01 = pk2(bv.x, bv.y);
            ull b23 = pk2(bv.z, bv.w);
            float am[4] = {av.x, av.y, av.z, av.w};
#pragma unroll
            for (int i = 0; i < 4; i++) {
                ull ad = pk2(am[i], am[i]);
                acc2[i][0] = fma2(b01, ad, acc2[i][0]);
                acc2[i][1] = fma2(b23, ad, acc2[i][1]);
            }
        }
        __syncthreads();
    }

#pragma unroll
    for (int i = 0; i < 4; i++) {
        int m = m0 + ty * 4 + i;
        if (m < M) {
            int n = n0 + tx * 4;
            float c0, c1, c2, c3;
            upk2(acc2[i][0], c0, c1);
            upk2(acc2[i][1], c2, c3);
            float4 o;
            o.x = scale * (c0 + bias[n + 0]);
            o.y = scale * (c1 + bias[n + 1]);
            o.z = scale * (c2 + bias[n + 2]);
            o.w = scale * (c3 + bias[n + 3]);
            *(float4*)&C[(size_t)m * 256 + n] = o;
        }
    }
}

// ---------------- fused attention ----------------
// SMEM (float offsets)
#define SM_Q     0        // [8][256]    2048  (broadcast reads; no pad needed)
#define SM_K     2048     // [32][260]   8320  (per-lane rows; pad)
#define SM_V     10368    // [32][256]   8192  (broadcast-ish reads)
#define SM_CPB0  18560    // [8*8][32]   2048  (cpb, exp'd in place -> p)
#define SM_CPB1  20608    // [8*8][32]   2048
#define SM_W1    22656    // float4[64]  (wx,wy,b,0)  256
#define SM_W2    22912    // ull[64][4]  head pairs   512
#define SM_B2    23424    // ull[4]                     8
#define SM_FLOATS 23432
#define SM_BYTES (SM_FLOATS * 4)

// store packed cpb accumulators (8 heads) for pair (bq,bk) into dst
__device__ __forceinline__ void cpb_store(
    float* __restrict__ dst, ull a0, ull a1, ull a2, ull a3,
    bool masked, int bq, int bk)
{
    float m = masked ? MASK_NEG : 0.f;
    float* base = dst + bq * 256 + bk;   // row (q*8+h)*32
    float e0, e1;
    upk2(a0, e0, e1); base[0]   = e0 + m; base[32]  = e1 + m;
    upk2(a1, e0, e1); base[64]  = e0 + m; base[96]  = e1 + m;
    upk2(a2, e0, e1); base[128] = e0 + m; base[160] = e1 + m;
    upk2(a3, e0, e1); base[192] = e0 + m; base[224] = e1 + m;
}

__global__ __launch_bounds__(256, 2) void attn_kernel(
    const float* __restrict__ rd, const unsigned char* __restrict__ mask,
    const float* __restrict__ Wc1, const float* __restrict__ bc1,
    const float* __restrict__ Wc2, const float* __restrict__ bc2)
{
    extern __shared__ __align__(16) float sm[];
    float*  q_s = sm + SM_Q;
    float*  k_s = sm + SM_K;
    float*  v_s = sm + SM_V;
    float4* w1  = (float4*)(sm + SM_W1);
    ull*    w2p = (ull*)(sm + SM_W2);
    ull*    b2p = (ull*)(sm + SM_B2);

    const int b  = blockIdx.y;
    const int q0 = blockIdx.x * QT;
    const int t  = threadIdx.x;
    const unsigned int smem_u32 = (unsigned int)__cvta_generic_to_shared(sm);

    // ---- prologue: q tile + weights ----
#pragma unroll
    for (int i = 0; i < 2; i++) {
        int idx = t + i * 256;            // 512 float4 = 8 rows x 64 chunks
        int qq  = idx >> 6, e4 = idx & 63;
        float4 val = make_float4(0.f, 0.f, 0.f, 0.f);
        if (q0 + qq < Qn)
            val = *(const float4*)&g_q[(size_t)((b * Qn) + (q0 + qq)) * En + e4 * 4];
        *(float4*)&q_s[qq * 256 + e4 * 4] = val;
    }
    if (t < 64) {
        w1[t] = make_float4(Wc1[2 * t], Wc1[2 * t + 1], bc1[t], 0.f);
#pragma unroll
        for (int hp = 0; hp < 4; hp++)
            w2p[t * 4 + hp] = pk2(Wc2[(2 * hp) * 64 + t], Wc2[(2 * hp + 1) * 64 + t]);
    }
    if (t < 4) b2p[t] = pk2(bc2[2 * t], bc2[2 * t + 1]);
    __syncthreads();

    // thread identities
    const int bq = t >> 5;        // cpb: query        (warp)
    const int bk = t & 31;        // cpb/B2 key lane
    const int wh = t >> 5;        // head owned by this warp (B2 & C)
    const int cq = bk >> 2;       // C: query
    const int dg = bk & 3;        // C: 8-dim group within head

    const int qg_b1 = q0 + bq;
    const size_t rd_row = ((size_t)b * Qn + (qg_b1 < Qn ? qg_b1 : Qn - 1)) * Kn;

    // ---- tile 0: async K/V load overlapped with CPB(0) compute ----
    {
#pragma unroll
        for (int i = 0; i < 8; i++) {
            int idx = t + i * 256;
            int kk  = idx >> 6, e4 = idx & 63;
            size_t gidx = (size_t)((b * Kn) + kk) * En + e4 * 4;
            cpa16(smem_u32 + (SM_K + kk * 260 + e4 * 4) * 4, &g_k[gidx]);
            cpa16(smem_u32 + (SM_V + kk * 256 + e4 * 4) * 4, &g_v[gidx]);
        }
        CP_COMMIT();
        float2 r2 = *(const float2*)&rd[(rd_row + bk) * 2];
        bool mk = mask[b * Kn + bk] != 0;
        ull a0 = b2p[0], a1 = b2p[1], a2 = b2p[2], a3 = b2p[3];
#pragma unroll 16
        for (int j = 0; j < 64; j++) {
            float4 w = w1[j];
            float hj = fmaxf(fmaf(w.x, r2.x, fmaf(w.y, r2.y, w.z)), 0.f);
            ull hd = pk2(hj, hj);
            ulonglong2 wa = *(const ulonglong2*)&w2p[j * 4];
            ulonglong2 wb = *(const ulonglong2*)&w2p[j * 4 + 2];
            a0 = fma2(wa.x, hd, a0);
            a1 = fma2(wa.y, hd, a1);
            a2 = fma2(wb.x, hd, a2);
            a3 = fma2(wb.y, hd, a3);
        }
        cpb_store(sm + SM_CPB0, a0, a1, a2, a3, mk, bq, bk);
        CP_WAIT0();
        __syncthreads();
    }

    float l_run = 0.f;
    float o[8];
#pragma unroll
    for (int d = 0; d < 8; d++) o[d] = 0.f;

    for (int it = 0; it < NTILES; it++) {
        const int k0 = it * KT;
        float* cpb_cur = sm + ((it & 1) ? SM_CPB1 : SM_CPB0);
        float* cpb_nxt = sm + ((it & 1) ? SM_CPB0 : SM_CPB1);

        // early LDG: rd/mask for next tile (in flight during B2)
        float dx = 0.f, dy = 0.f;
        bool mk = false;
        if (it + 1 < NTILES) {
            float2 r2 = *(const float2*)&rd[(rd_row + k0 + KT + bk) * 2];
            dx = r2.x; dy = r2.y;
            mk = mask[b * Kn + k0 + KT + bk] != 0;
        }

        // ===== B2: QK dot (packed f32x2) + exp, in place =====
        {
            ull kf2[16];
#pragma unroll
            for (int i = 0; i < 8; i++) {
                float4 v4 = *(const float4*)&k_s[bk * 260 + wh * 32 + i * 4];
                kf2[2 * i]     = pk2(v4.x, v4.y);
                kf2[2 * i + 1] = pk2(v4.z, v4.w);
            }
#pragma unroll
            for (int q = 0; q < 8; q++) {
                const float* qr = &q_s[q * 256 + wh * 32];
                float4 q4 = *(const float4*)&qr[0];
                ull d2 = mul2(pk2(q4.x, q4.y), kf2[0]);
                d2 = fma2(pk2(q4.z, q4.w), kf2[1], d2);
#pragma unroll
                for (int i = 1; i < 8; i++) {
                    float4 qv = *(const float4*)&qr[i * 4];
                    d2 = fma2(pk2(qv.x, qv.y), kf2[2 * i], d2);
                    d2 = fma2(pk2(qv.z, qv.w), kf2[2 * i + 1], d2);
                }
                float lo, hi; upk2(d2, lo, hi);
                int ad = (q * 8 + wh) * 32 + bk;
                cpb_cur[ad] = __expf(lo + hi + cpb_cur[ad]);
            }
        }
        CP_WAIT0();           // V(it) landed (issued last iter; no-op at it=0)
        __syncthreads();      // p visible; k_s free; v_s visible

        // issue K(it+1) — hidden behind C+CPB below
        if (it + 1 < NTILES) {
#pragma unroll
            for (int i = 0; i < 8; i++) {
                int idx = t + i * 256;
                int kk  = idx >> 6, e4 = idx & 63;
                size_t gidx = (size_t)((b * Kn) + (k0 + KT + kk)) * En + e4 * 4;
                cpa16(smem_u32 + (SM_K + kk * 260 + e4 * 4) * 4, &g_k[gidx]);
            }
            CP_COMMIT();
        }

        // ===== fused: C (AV accumulate) + CPB(it+1) interleaved =====
        ull a0 = b2p[0], a1 = b2p[1], a2 = b2p[2], a3 = b2p[3];
        {
            const float* pr = &cpb_cur[(cq * 8 + wh) * 32];
            const float* vb = &v_s[wh * 32 + dg * 8];
#pragma unroll 8
            for (int i = 0; i < 32; i++) {
#pragma unroll
                for (int jj = 0; jj < 2; jj++) {
                    int j = 2 * i + jj;
                    float4 w = w1[j];
                    float hj = fmaxf(fmaf(w.x, dx, fmaf(w.y, dy, w.z)), 0.f);
                    ull hd = pk2(hj, hj);
                    ulonglong2 wa = *(const ulonglong2*)&w2p[j * 4];
                    ulonglong2 wb = *(const ulonglong2*)&w2p[j * 4 + 2];
                    a0 = fma2(wa.x, hd, a0);
                    a1 = fma2(wa.y, hd, a1);
                    a2 = fma2(wb.x, hd, a2);
                    a3 = fma2(wb.y, hd, a3);
                }
                float p = pr[i];
                l_run += p;
                float4 va = *(const float4*)&vb[i * 256];
                float4 v2 = *(const float4*)&vb[i * 256 + 4];
                o[0] = fmaf(p, va.x, o[0]);
                o[1] = fmaf(p, va.y, o[1]);
                o[2] = fmaf(p, va.z, o[2]);
                o[3] = fmaf(p, va.w, o[3]);
                o[4] = fmaf(p, v2.x, o[4]);
                o[5] = fmaf(p, v2.y, o[5]);
                o[6] = fmaf(p, v2.z, o[6]);
                o[7] = fmaf(p, v2.w, o[7]);
            }
        }
        __syncthreads();      // v_s free; cpb_nxt free (consumed 2 tiles ago)

        if (it + 1 < NTILES) {
            // issue V(it+1); its latency hides behind B2-next
#pragma unroll
            for (int i = 0; i < 8; i++) {
                int idx = t + i * 256;
                int kk  = idx >> 6, e4 = idx & 63;
                size_t gidx = (size_t)((b * Kn) + (k0 + KT + kk)) * En + e4 * 4;
                cpa16(smem_u32 + (SM_V + kk * 256 + e4 * 4) * 4, &g_v[gidx]);
            }
            CP_COMMIT();
            cpb_store(cpb_nxt, a0, a1, a2, a3, mk, bq, bk);
            CP_WAIT1();        // K(it+1) landed; V(it+1) may still fly
            __syncthreads();   // k_s + cpb_nxt visible for next B2
        }
    }

    // ---- epilogue: lane (cq,dg) owns dims [wh*32+dg*8, +8) of query cq ----
    int qg = q0 + cq;
    if (qg < Qn) {
        float inv = 1.f / l_run;
        float* dst = &g_att[(size_t)((b * Qn) + qg) * En + wh * 32 + dg * 8];
        *(float4*)&dst[0] = make_float4(o[0] * inv, o[1] * inv, o[2] * inv, o[3] * inv);
        *(float4*)&dst[4] = make_float4(o[4] * inv, o[5] * inv, o[6] * inv, o[7] * inv);
    }
}

// ---------------- launch ----------------
extern "C" void kernel_launch(void* const* d_in, const int* in_sizes, int n_in,
                              void* d_out, int out_size)
{
    const float*         nodes  = (const float*)d_in[0];
    const float*         images = (const float*)d_in[1];
    const unsigned char* imask  = (const unsigned char*)d_in[2];
    const float*         rd     = (const float*)d_in[3];
    const float*         Wq     = (const float*)d_in[4];
    const float*         bq     = (const float*)d_in[5];
    const float*         Wkv    = (const float*)d_in[6];
    const float*         bkv    = (const float*)d_in[7];
    const float*         Wc1    = (const float*)d_in[8];
    const float*         bc1    = (const float*)d_in[9];
    const float*         Wc2    = (const float*)d_in[10];
    const float*         bc2    = (const float*)d_in[11];
    const float*         Wo     = (const float*)d_in[12];
    const float*         bo     = (const float*)d_in[13];
    float*               out    = (float*)d_out;

    float *pq, *pk, *pv, *pa;
    cudaGetSymbolAddress((void**)&pq, g_q);
    cudaGetSymbolAddress((void**)&pk, g_k);
    cudaGetSymbolAddress((void**)&pv, g_v);
    cudaGetSymbolAddress((void**)&pa, g_att);

    const int MQ = Bn * Qn;   // 3600
    const int MK = Bn * Kn;   // 4096

    {
        dim3 g((MQ + 63) / 64, 4);
        proj_gemm<<<g, 256>>>(nodes, Wq, bq, pq, MQ, SCALE_Q);
    }
    {
        dim3 g((MK + 63) / 64, 4);
        proj_gemm<<<g, 256>>>(images, Wkv,             bkv,       pk, MK, 1.f);
        proj_gemm<<<g, 256>>>(images, Wkv + 256 * 256, bkv + 256, pv, MK, 1.f);
    }
    {
        cudaFuncSetAttribute(attn_kernel,
                             cudaFuncAttributeMaxDynamicSharedMemorySize, SM_BYTES);
        dim3 g((Qn + QT - 1) / QT, Bn);   // (113, 4) = 452 CTAs
        attn_kernel<<<g, 256, SM_BYTES>>>(rd, imask, Wc1, bc1, Wc2, bc2);
    }
    {
        dim3 g((MQ + 63) / 64, 4);
        proj_gemm<<<g, 256>>>(pa, Wo, bo, out, MQ, 1.f);
    }
}

// round 6
// speedup vs baseline: 1.6275x; 1.1192x over previous
#include <cuda_runtime.h>
#include <cuda_bf16.h>
#include <math.h>

// ---------------- problem constants ----------------
#define Bn 4
#define Qn 900
#define Kn 1024
#define En 256
#define Hn 8
#define Dn 32
#define QT 8
#define KT 32
#define NTILES (Kn / KT)
#define SCALE_Q 0.17677669529663687f  // 1/sqrt(32)
#define MASK_NEG (-10000.0f)

typedef unsigned long long ull;

// ---------------- f32x2 packed helpers ----------------
__device__ __forceinline__ ull pk2(float lo, float hi) {
    ull r; asm("mov.b64 %0, {%1,%2};" : "=l"(r) : "f"(lo), "f"(hi)); return r;
}
__device__ __forceinline__ void upk2(ull v, float& lo, float& hi) {
    asm("mov.b64 {%0,%1}, %2;" : "=f"(lo), "=f"(hi) : "l"(v));
}
__device__ __forceinline__ ull fma2(ull a, ull b, ull c) {
    ull r; asm("fma.rn.f32x2 %0, %1, %2, %3;" : "=l"(r) : "l"(a), "l"(b), "l"(c)); return r;
}
__device__ __forceinline__ ull mul2(ull a, ull b) {
    ull r; asm("mul.rn.f32x2 %0, %1, %2;" : "=l"(r) : "l"(a), "l"(b)); return r;
}

// ---------------- tf32 mma helpers ----------------
__device__ __forceinline__ unsigned f2tf(float f) {
    unsigned r; asm("cvt.rna.tf32.f32 %0, %1;" : "=r"(r) : "f"(f)); return r;
}
__device__ __forceinline__ void mma_tf32(float c[4],
    unsigned a0, unsigned a1, unsigned a2, unsigned a3,
    unsigned b0, unsigned b1)
{
    asm volatile(
        "mma.sync.aligned.m16n8k8.row.col.f32.tf32.tf32.f32 "
        "{%0,%1,%2,%3}, {%4,%5,%6,%7}, {%8,%9}, {%0,%1,%2,%3};"
        : "+f"(c[0]), "+f"(c[1]), "+f"(c[2]), "+f"(c[3])
        : "r"(a0), "r"(a1), "r"(a2), "r"(a3), "r"(b0), "r"(b1));
}

// ---------------- cp.async helpers ----------------
__device__ __forceinline__ void cpa16(unsigned int dst, const void* src) {
    asm volatile("cp.async.cg.shared.global [%0], [%1], 16;" :: "r"(dst), "l"(src));
}
#define CP_COMMIT() asm volatile("cp.async.commit_group;")
#define CP_WAIT0()  asm volatile("cp.async.wait_group 0;" ::: "memory")
#define CP_WAIT1()  asm volatile("cp.async.wait_group 1;" ::: "memory")

// ---------------- scratch ----------------
__device__ __align__(16) float g_q[Bn * Qn * En];
__device__ __align__(16) float g_k[Bn * Kn * En];
__device__ __align__(16) float g_v[Bn * Kn * En];
__device__ __align__(16) float g_att[Bn * Qn * En];

// ---------------- projection GEMM ----------------
__global__ __launch_bounds__(256) void proj_gemm(
    const float* __restrict__ A, const float* __restrict__ W,
    const float* __restrict__ bias, float* __restrict__ C,
    int M, float scale)
{
    __shared__ __align__(16) float As[16][64];
    __shared__ __align__(16) float Bs[16][64];

    const int m0 = blockIdx.x * 64;
    const int n0 = blockIdx.y * 64;
    const int t  = threadIdx.x;
    const int tx = t & 15;
    const int ty = t >> 4;
    const int lr = t >> 2;
    const int lc = (t & 3) * 4;

    ull acc2[4][2];
#pragma unroll
    for (int i = 0; i < 4; i++) { acc2[i][0] = 0ULL; acc2[i][1] = 0ULL; }

    for (int k0 = 0; k0 < 256; k0 += 16) {
        float4 a4 = make_float4(0.f, 0.f, 0.f, 0.f);
        if (m0 + lr < M)
            a4 = *(const float4*)&A[(size_t)(m0 + lr) * 256 + k0 + lc];
        As[lc + 0][lr] = a4.x; As[lc + 1][lr] = a4.y;
        As[lc + 2][lr] = a4.z; As[lc + 3][lr] = a4.w;

        float4 b4 = *(const float4*)&W[(size_t)(n0 + lr) * 256 + k0 + lc];
        Bs[lc + 0][lr] = b4.x; Bs[lc + 1][lr] = b4.y;
        Bs[lc + 2][lr] = b4.z; Bs[lc + 3][lr] = b4.w;
        __syncthreads();

#pragma unroll
        for (int kk = 0; kk < 16; kk++) {
            float4 av = *(const float4*)&As[kk][ty * 4];
            float4 bv = *(const float4*)&Bs[kk][tx * 4];
            ull b01 = pk2(bv.x, bv.y);
            ull b23 = pk2(bv.z, bv.w);
            float am[4] = {av.x, av.y, av.z, av.w};
#pragma unroll
            for (int i = 0; i < 4; i++) {
                ull ad = pk2(am[i], am[i]);
                acc2[i][0] = fma2(b01, ad, acc2[i][0]);
                acc2[i][1] = fma2(b23, ad, acc2[i][1]);
            }
        }
        __syncthreads();
    }

#pragma unroll
    for (int i = 0; i < 4; i++) {
        int m = m0 + ty * 4 + i;
        if (m < M) {
            int n = n0 + tx * 4;
            float c0, c1, c2, c3;
            upk2(acc2[i][0], c0, c1);
            upk2(acc2[i][1], c2, c3);
            float4 o;
            o.x = scale * (c0 + bias[n + 0]);
            o.y = scale * (c1 + bias[n + 1]);
            o.z = scale * (c2 + bias[n + 2]);
            o.w = scale * (c3 + bias[n + 3]);
            *(float4*)&C[(size_t)m * 256 + n] = o;
        }
    }
}

// ---------------- fused attention ----------------
// SMEM (float offsets)
#define SM_Q     0        // [8][256]    2048
#define SM_K     2048     // [32][260]   8320
#define SM_V     10368    // [32][256]   8192
#define SM_CPB0  18560    // [8*8][32]   2048
#define SM_CPB1  20608    // [8*8][32]   2048
#define SM_W1    22656    // float4[64]  (wx,wy,b,0)  256
#define SM_FLOATS 22912
#define SM_BYTES (SM_FLOATS * 4)

// CPB layer2 via tf32 mma: warp = query, M=32 keys (2 m16 tiles), N=8 heads, K=64 (8 steps).
// Wc2 fragments (bf0/bf1, tf32) live in registers. A (hidden) computed fp32, split-tf32 2-pass.
// dx,dy,maddend: this thread's pair (q=warp, key=lane). Stores biased+masked cpb to dst.
__device__ __forceinline__ void cpb_mma(
    float* __restrict__ dst, const float4* __restrict__ w1,
    const unsigned* __restrict__ bf0, const unsigned* __restrict__ bf1,
    float bias0, float bias1,
    float dx, float dy, float maddend, int lane, int warp)
{
    float dxr[4], dyr[4], mr[4];
#pragma unroll
    for (int g = 0; g < 4; g++) {
        int src = (lane >> 2) + g * 8;
        dxr[g] = __shfl_sync(0xffffffffu, dx, src);
        dyr[g] = __shfl_sync(0xffffffffu, dy, src);
        mr[g]  = __shfl_sync(0xffffffffu, maddend, src);
    }
    float c0[4], c1[4];
    c0[0] = c0[2] = bias0; c0[1] = c0[3] = bias1;
    c1[0] = c1[2] = bias0; c1[1] = c1[3] = bias1;
#pragma unroll
    for (int s = 0; s < 8; s++) {
        float4 wA = w1[s * 8 + (lane & 3)];
        float4 wB = w1[s * 8 + 4 + (lane & 3)];
        unsigned b0 = bf0[s], b1 = bf1[s];
#pragma unroll
        for (int mt = 0; mt < 2; mt++) {
            float xa = dxr[2 * mt], ya = dyr[2 * mt];
            float xb = dxr[2 * mt + 1], yb = dyr[2 * mt + 1];
            float h00 = fmaxf(fmaf(wA.x, xa, fmaf(wA.y, ya, wA.z)), 0.f);
            float h10 = fmaxf(fmaf(wA.x, xb, fmaf(wA.y, yb, wA.z)), 0.f);
            float h01 = fmaxf(fmaf(wB.x, xa, fmaf(wB.y, ya, wB.z)), 0.f);
            float h11 = fmaxf(fmaf(wB.x, xb, fmaf(wB.y, yb, wB.z)), 0.f);
            unsigned a0 = f2tf(h00), a1 = f2tf(h10), a2 = f2tf(h01), a3 = f2tf(h11);
            unsigned l0 = f2tf(h00 - __uint_as_float(a0));
            unsigned l1 = f2tf(h10 - __uint_as_float(a1));
            unsigned l2 = f2tf(h01 - __uint_as_float(a2));
            unsigned l3 = f2tf(h11 - __uint_as_float(a3));
            float* cc = mt ? c1 : c0;
            mma_tf32(cc, l0, l1, l2, l3, b0, b1);   // low part first
            mma_tf32(cc, a0, a1, a2, a3, b0, b1);
        }
    }
    const int m2 = lane & 3, r = lane >> 2;
    float* base = dst + warp * 256;
#pragma unroll
    for (int mt = 0; mt < 2; mt++) {
        float* cc = mt ? c1 : c0;
        int kr = r + mt * 16;
        base[(2 * m2)     * 32 + kr]     = cc[0] + mr[2 * mt];
        base[(2 * m2 + 1) * 32 + kr]     = cc[1] + mr[2 * mt];
        base[(2 * m2)     * 32 + kr + 8] = cc[2] + mr[2 * mt + 1];
        base[(2 * m2 + 1) * 32 + kr + 8] = cc[3] + mr[2 * mt + 1];
    }
}

__global__ __launch_bounds__(256, 2) void attn_kernel(
    const float* __restrict__ rd, const unsigned char* __restrict__ mask,
    const float* __restrict__ Wc1, const float* __restrict__ bc1,
    const float* __restrict__ Wc2, const float* __restrict__ bc2)
{
    extern __shared__ __align__(16) float sm[];
    float*  q_s = sm + SM_Q;
    float*  k_s = sm + SM_K;
    float*  v_s = sm + SM_V;
    float4* w1  = (float4*)(sm + SM_W1);

    const int b  = blockIdx.y;
    const int q0 = blockIdx.x * QT;
    const int t  = threadIdx.x;
    const unsigned int smem_u32 = (unsigned int)__cvta_generic_to_shared(sm);

    const int wh = t >> 5;        // warp = query (cpb) = head (B2/C)
    const int bk = t & 31;        // lane = key
    const int cq = bk >> 2;       // C: query
    const int dg = bk & 3;        // C: 8-dim group

    // ---- prologue: q tile + w1 + per-thread Wc2 fragments ----
#pragma unroll
    for (int i = 0; i < 2; i++) {
        int idx = t + i * 256;
        int qq  = idx >> 6, e4 = idx & 63;
        float4 val = make_float4(0.f, 0.f, 0.f, 0.f);
        if (q0 + qq < Qn)
            val = *(const float4*)&g_q[(size_t)((b * Qn) + (q0 + qq)) * En + e4 * 4];
        *(float4*)&q_s[qq * 256 + e4 * 4] = val;
    }
    if (t < 64)
        w1[t] = make_float4(Wc1[2 * t], Wc1[2 * t + 1], bc1[t], 0.f);

    // Wc2^T fragments: head = lane/4 (n), j = s*8 + lane%4 (+4)
    unsigned bf0[8], bf1[8];
    {
        const int hd = bk >> 2, jc = bk & 3;
#pragma unroll
        for (int s = 0; s < 8; s++) {
            bf0[s] = f2tf(Wc2[hd * 64 + s * 8 + jc]);
            bf1[s] = f2tf(Wc2[hd * 64 + s * 8 + 4 + jc]);
        }
    }
    const float bias0 = bc2[2 * (bk & 3)];
    const float bias1 = bc2[2 * (bk & 3) + 1];
    __syncthreads();

    const int qg_b1 = q0 + wh;
    const size_t rd_row = ((size_t)b * Qn + (qg_b1 < Qn ? qg_b1 : Qn - 1)) * Kn;

    // ---- tile 0: async K/V load overlapped with CPB(0) mma ----
    {
#pragma unroll
        for (int i = 0; i < 8; i++) {
            int idx = t + i * 256;
            int kk  = idx >> 6, e4 = idx & 63;
            size_t gidx = (size_t)((b * Kn) + kk) * En + e4 * 4;
            cpa16(smem_u32 + (SM_K + kk * 260 + e4 * 4) * 4, &g_k[gidx]);
            cpa16(smem_u32 + (SM_V + kk * 256 + e4 * 4) * 4, &g_v[gidx]);
        }
        CP_COMMIT();
        float2 r2 = *(const float2*)&rd[(rd_row + bk) * 2];
        float ma = (mask[b * Kn + bk] != 0) ? MASK_NEG : 0.f;
        cpb_mma(sm + SM_CPB0, w1, bf0, bf1, bias0, bias1, r2.x, r2.y, ma, bk, wh);
        CP_WAIT0();
        __syncthreads();
    }

    float l_run = 0.f;
    float o[8];
#pragma unroll
    for (int d = 0; d < 8; d++) o[d] = 0.f;

    for (int it = 0; it < NTILES; it++) {
        const int k0 = it * KT;
        float* cpb_cur = sm + ((it & 1) ? SM_CPB1 : SM_CPB0);
        float* cpb_nxt = sm + ((it & 1) ? SM_CPB0 : SM_CPB1);

        // early LDG: rd/mask for next tile (in flight during B2)
        float dx = 0.f, dy = 0.f, ma = 0.f;
        if (it + 1 < NTILES) {
            float2 r2 = *(const float2*)&rd[(rd_row + k0 + KT + bk) * 2];
            dx = r2.x; dy = r2.y;
            ma = (mask[b * Kn + k0 + KT + bk] != 0) ? MASK_NEG : 0.f;
        }

        // ===== B2: QK dot (packed f32x2) + exp, in place =====
        {
            ull kf2[16];
#pragma unroll
            for (int i = 0; i < 8; i++) {
                float4 v4 = *(const float4*)&k_s[bk * 260 + wh * 32 + i * 4];
                kf2[2 * i]     = pk2(v4.x, v4.y);
                kf2[2 * i + 1] = pk2(v4.z, v4.w);
            }
#pragma unroll
            for (int q = 0; q < 8; q++) {
                const float* qr = &q_s[q * 256 + wh * 32];
                float4 q4 = *(const float4*)&qr[0];
                ull d2 = mul2(pk2(q4.x, q4.y), kf2[0]);
                d2 = fma2(pk2(q4.z, q4.w), kf2[1], d2);
#pragma unroll
                for (int i = 1; i < 8; i++) {
                    float4 qv = *(const float4*)&qr[i * 4];
                    d2 = fma2(pk2(qv.x, qv.y), kf2[2 * i], d2);
                    d2 = fma2(pk2(qv.z, qv.w), kf2[2 * i + 1], d2);
                }
                float lo, hi; upk2(d2, lo, hi);
                int ad = (q * 8 + wh) * 32 + bk;
                cpb_cur[ad] = __expf(lo + hi + cpb_cur[ad]);
            }
        }
        CP_WAIT0();           // V(it) landed
        __syncthreads();      // p visible; k_s free; v_s visible

        // issue K(it+1)
        if (it + 1 < NTILES) {
#pragma unroll
            for (int i = 0; i < 8; i++) {
                int idx = t + i * 256;
                int kk  = idx >> 6, e4 = idx & 63;
                size_t gidx = (size_t)((b * Kn) + (k0 + KT + kk)) * En + e4 * 4;
                cpa16(smem_u32 + (SM_K + kk * 260 + e4 * 4) * 4, &g_k[gidx]);
            }
            CP_COMMIT();
        }

        // ===== C: AV accumulate =====
        {
            const float* pr = &cpb_cur[(cq * 8 + wh) * 32];
            const float* vb = &v_s[wh * 32 + dg * 8];
#pragma unroll 8
            for (int kl = 0; kl < KT; kl++) {
                float p = pr[kl];
                l_run += p;
                float4 va = *(const float4*)&vb[kl * 256];
                float4 v2 = *(const float4*)&vb[kl * 256 + 4];
                o[0] = fmaf(p, va.x, o[0]);
                o[1] = fmaf(p, va.y, o[1]);
                o[2] = fmaf(p, va.z, o[2]);
                o[3] = fmaf(p, va.w, o[3]);
                o[4] = fmaf(p, v2.x, o[4]);
                o[5] = fmaf(p, v2.y, o[5]);
                o[6] = fmaf(p, v2.z, o[6]);
                o[7] = fmaf(p, v2.w, o[7]);
            }
        }

        // ===== CPB(it+1): tf32 mma, stores into cpb_nxt (safe: last read 2 barriers ago) =====
        if (it + 1 < NTILES)
            cpb_mma(cpb_nxt, w1, bf0, bf1, bias0, bias1, dx, dy, ma, bk, wh);

        __syncthreads();      // v_s free

        if (it + 1 < NTILES) {
#pragma unroll
            for (int i = 0; i < 8; i++) {
                int idx = t + i * 256;
                int kk  = idx >> 6, e4 = idx & 63;
                size_t gidx = (size_t)((b * Kn) + (k0 + KT + kk)) * En + e4 * 4;
                cpa16(smem_u32 + (SM_V + kk * 256 + e4 * 4) * 4, &g_v[gidx]);
            }
            CP_COMMIT();
            CP_WAIT1();        // K(it+1) landed; V(it+1) still in flight
            __syncthreads();   // k_s + cpb_nxt visible for next B2
        }
    }

    // ---- epilogue ----
    int qg = q0 + cq;
    if (qg < Qn) {
        float inv = 1.f / l_run;
        float* dst = &g_att[(size_t)((b * Qn) + qg) * En + wh * 32 + dg * 8];
        *(float4*)&dst[0] = make_float4(o[0] * inv, o[1] * inv, o[2] * inv, o[3] * inv);
        *(float4*)&dst[4] = make_float4(o[4] * inv, o[5] * inv, o[6] * inv, o[7] * inv);
    }
}

// ---------------- launch ----------------
extern "C" void kernel_launch(void* const* d_in, const int* in_sizes, int n_in,
                              void* d_out, int out_size)
{
    const float*         nodes  = (const float*)d_in[0];
    const float*         images = (const float*)d_in[1];
    const unsigned char* imask  = (const unsigned char*)d_in[2];
    const float*         rd     = (const float*)d_in[3];
    const float*         Wq     = (const float*)d_in[4];
    const float*         bq     = (const float*)d_in[5];
    const float*         Wkv    = (const float*)d_in[6];
    const float*         bkv    = (const float*)d_in[7];
    const float*         Wc1    = (const float*)d_in[8];
    const float*         bc1    = (const float*)d_in[9];
    const float*         Wc2    = (const float*)d_in[10];
    const float*         bc2    = (const float*)d_in[11];
    const float*         Wo     = (const float*)d_in[12];
    const float*         bo     = (const float*)d_in[13];
    float*               out    = (float*)d_out;

    float *pq, *pk, *pv, *pa;
    cudaGetSymbolAddress((void**)&pq, g_q);
    cudaGetSymbolAddress((void**)&pk, g_k);
    cudaGetSymbolAddress((void**)&pv, g_v);
    cudaGetSymbolAddress((void**)&pa, g_att);

    const int MQ = Bn * Qn;   // 3600
    const int MK = Bn * Kn;   // 4096

    {
        dim3 g((MQ + 63) / 64, 4);
        proj_gemm<<<g, 256>>>(nodes, Wq, bq, pq, MQ, SCALE_Q);
    }
    {
        dim3 g((MK + 63) / 64, 4);
        proj_gemm<<<g, 256>>>(images, Wkv,             bkv,       pk, MK, 1.f);
        proj_gemm<<<g, 256>>>(images, Wkv + 256 * 256, bkv + 256, pv, MK, 1.f);
    }
    {
        cudaFuncSetAttribute(attn_kernel,
                             cudaFuncAttributeMaxDynamicSharedMemorySize, SM_BYTES);
        dim3 g((Qn + QT - 1) / QT, Bn);   // (113, 4) = 452 CTAs
        attn_kernel<<<g, 256, SM_BYTES>>>(rd, imask, Wc1, bc1, Wc2, bc2);
    }
    {
        dim3 g((MQ + 63) / 64, 4);
        proj_gemm<<<g, 256>>>(pa, Wo, bo, out, MQ, 1.f);
    }
}

// round 8
// speedup vs baseline: 3.1055x; 1.9082x over previous
#include <cuda_runtime.h>
#include <cuda_bf16.h>
#include <math.h>

// ---------------- problem constants ----------------
#define Bn 4
#define Qn 900
#define Kn 1024
#define En 256
#define Hn 8
#define Dn 32
#define QT 8
#define KT 32
#define NTILES (Kn / KT)
#define SCALE_Q 0.17677669529663687f  // 1/sqrt(32)
#define MASK_NEG (-10000.0f)

typedef unsigned long long ull;

// ---------------- f32x2 packed helpers (proj gemm) ----------------
__device__ __forceinline__ ull pk2(float lo, float hi) {
    ull r; asm("mov.b64 %0, {%1,%2};" : "=l"(r) : "f"(lo), "f"(hi)); return r;
}
__device__ __forceinline__ void upk2(ull v, float& lo, float& hi) {
    asm("mov.b64 {%0,%1}, %2;" : "=f"(lo), "=f"(hi) : "l"(v));
}
__device__ __forceinline__ ull fma2(ull a, ull b, ull c) {
    ull r; asm("fma.rn.f32x2 %0, %1, %2, %3;" : "=l"(r) : "l"(a), "l"(b), "l"(c)); return r;
}

// ---------------- tf32 mma helpers ----------------
__device__ __forceinline__ unsigned f2tf(float f) {
    unsigned r; asm("cvt.rna.tf32.f32 %0, %1;" : "=r"(r) : "f"(f)); return r;
}
__device__ __forceinline__ void mma_tf32(float c[4],
    unsigned a0, unsigned a1, unsigned a2, unsigned a3,
    unsigned b0, unsigned b1)
{
    asm volatile(
        "mma.sync.aligned.m16n8k8.row.col.f32.tf32.tf32.f32 "
        "{%0,%1,%2,%3}, {%4,%5,%6,%7}, {%8,%9}, {%0,%1,%2,%3};"
        : "+f"(c[0]), "+f"(c[1]), "+f"(c[2]), "+f"(c[3])
        : "r"(a0), "r"(a1), "r"(a2), "r"(a3), "r"(b0), "r"(b1));
}
__device__ __forceinline__ void ldsm4(unsigned& r0, unsigned& r1,
                                      unsigned& r2, unsigned& r3, unsigned addr)
{
    asm volatile("ldmatrix.sync.aligned.m8n8.x4.shared.b16 {%0,%1,%2,%3}, [%4];"
                 : "=r"(r0), "=r"(r1), "=r"(r2), "=r"(r3) : "r"(addr));
}

// ---------------- cp.async helpers ----------------
__device__ __forceinline__ void cpa16(unsigned int dst, const void* src) {
    asm volatile("cp.async.cg.shared.global [%0], [%1], 16;" :: "r"(dst), "l"(src));
}
#define CP_COMMIT() asm volatile("cp.async.commit_group;")
#define CP_WAIT0()  asm volatile("cp.async.wait_group 0;" ::: "memory")
#define CP_WAIT1()  asm volatile("cp.async.wait_group 1;" ::: "memory")

// ---------------- scratch ----------------
__device__ __align__(16) float g_q[Bn * Qn * En];
__device__ __align__(16) float g_k[Bn * Kn * En];
__device__ __align__(16) float g_v[Bn * Kn * En];
__device__ __align__(16) float g_att[Bn * Qn * En];

// ---------------- projection GEMM ----------------
__global__ __launch_bounds__(256) void proj_gemm(
    const float* __restrict__ A, const float* __restrict__ W,
    const float* __restrict__ bias, float* __restrict__ C,
    int M, float scale)
{
    __shared__ __align__(16) float As[16][64];
    __shared__ __align__(16) float Bs[16][64];

    const int m0 = blockIdx.x * 64;
    const int n0 = blockIdx.y * 64;
    const int t  = threadIdx.x;
    const int tx = t & 15;
    const int ty = t >> 4;
    const int lr = t >> 2;
    const int lc = (t & 3) * 4;

    ull acc2[4][2];
#pragma unroll
    for (int i = 0; i < 4; i++) { acc2[i][0] = 0ULL; acc2[i][1] = 0ULL; }

    for (int k0 = 0; k0 < 256; k0 += 16) {
        float4 a4 = make_float4(0.f, 0.f, 0.f, 0.f);
        if (m0 + lr < M)
            a4 = *(const float4*)&A[(size_t)(m0 + lr) * 256 + k0 + lc];
        As[lc + 0][lr] = a4.x; As[lc + 1][lr] = a4.y;
        As[lc + 2][lr] = a4.z; As[lc + 3][lr] = a4.w;

        float4 b4 = *(const float4*)&W[(size_t)(n0 + lr) * 256 + k0 + lc];
        Bs[lc + 0][lr] = b4.x; Bs[lc + 1][lr] = b4.y;
        Bs[lc + 2][lr] = b4.z; Bs[lc + 3][lr] = b4.w;
        __syncthreads();

#pragma unroll
        for (int kk = 0; kk < 16; kk++) {
            float4 av = *(const float4*)&As[kk][ty * 4];
            float4 bv = *(const float4*)&Bs[kk][tx * 4];
            ull b01 = pk2(bv.x, bv.y);
            ull b23 = pk2(bv.z, bv.w);
            float am[4] = {av.x, av.y, av.z, av.w};
#pragma unroll
            for (int i = 0; i < 4; i++) {
                ull ad = pk2(am[i], am[i]);
                acc2[i][0] = fma2(b01, ad, acc2[i][0]);
                acc2[i][1] = fma2(b23, ad, acc2[i][1]);
            }
        }
        __syncthreads();
    }

#pragma unroll
    for (int i = 0; i < 4; i++) {
        int m = m0 + ty * 4 + i;
        if (m < M) {
            int n = n0 + tx * 4;
            float c0, c1, c2, c3;
            upk2(acc2[i][0], c0, c1);
            upk2(acc2[i][1], c2, c3);
            float4 o;
            o.x = scale * (c0 + bias[n + 0]);
            o.y = scale * (c1 + bias[n + 1]);
            o.z = scale * (c2 + bias[n + 2]);
            o.w = scale * (c3 + bias[n + 3]);
            *(float4*)&C[(size_t)m * 256 + n] = o;
        }
    }
}

// ---------------- fused attention (full tensor-core) ----------------
// SMEM (float offsets)
#define SM_K     0        // [32][260]   8320  (ldmatrix rows; 16B bank rotation)
#define SM_V     8320     // [32][264]   8448  (scalar A-frag loads; 8*key+d bijection)
#define SM_CPB0  16768    // [64][36]    2304  rows = h*8+q, key XOR-swizzled by 8*((h>>1)&3)
#define SM_CPB1  19072    // [64][36]    2304
#define SM_W1    21376    // float4[64]  (wx,wy,b,0)  256
#define SM_FLOATS 21632
#define SM_BYTES (SM_FLOATS * 4)

// CPB layer-2 via tf32 mma. warp = query wq; A = hidden[32 keys x 64], B = Wc2^T (regs).
// Single-pass tf32 (h truncated). Stores biased+masked cpb into dst.
__device__ __forceinline__ void cpb_tile(
    float* __restrict__ dst, const float4* __restrict__ w1,
    const unsigned* __restrict__ bf0, const unsigned* __restrict__ bf1,
    float bias0, float bias1,
    const float* dxr, const float* dyr, const float* mr, int lane, int wq)
{
    float c0[4], c1[4];
    c0[0] = c0[2] = bias0; c0[1] = c0[3] = bias1;
    c1[0] = c1[2] = bias0; c1[1] = c1[3] = bias1;
#pragma unroll
    for (int s = 0; s < 8; s++) {
        float4 wA = w1[s * 8 + (lane & 3)];
        float4 wB = w1[s * 8 + 4 + (lane & 3)];
        unsigned b0 = bf0[s], b1 = bf1[s];
#pragma unroll
        for (int mt = 0; mt < 2; mt++) {
            float h00 = fmaxf(fmaf(wA.x, dxr[2*mt],   fmaf(wA.y, dyr[2*mt],   wA.z)), 0.f);
            float h10 = fmaxf(fmaf(wA.x, dxr[2*mt+1], fmaf(wA.y, dyr[2*mt+1], wA.z)), 0.f);
            float h01 = fmaxf(fmaf(wB.x, dxr[2*mt],   fmaf(wB.y, dyr[2*mt],   wB.z)), 0.f);
            float h11 = fmaxf(fmaf(wB.x, dxr[2*mt+1], fmaf(wB.y, dyr[2*mt+1], wB.z)), 0.f);
            float* cc = mt ? c1 : c0;
            mma_tf32(cc, __float_as_uint(h00), __float_as_uint(h10),
                         __float_as_uint(h01), __float_as_uint(h11), b0, b1);
        }
    }
    const int kswz = 8 * (lane & 3);           // = 8*((h>>1)&3) for h = 2(lane&3)+j
    const int h0 = 2 * (lane & 3), h1 = h0 + 1;
#pragma unroll
    for (int mt = 0; mt < 2; mt++) {
        float* cc = mt ? c1 : c0;
        int key0 = (lane >> 2) + 16 * mt;
        int key1 = key0 + 8;
        dst[(h0 * 8 + wq) * 36 + (key0 ^ kswz)] = cc[0] + mr[2*mt];
        dst[(h1 * 8 + wq) * 36 + (key0 ^ kswz)] = cc[1] + mr[2*mt];
        dst[(h0 * 8 + wq) * 36 + (key1 ^ kswz)] = cc[2] + mr[2*mt+1];
        dst[(h1 * 8 + wq) * 36 + (key1 ^ kswz)] = cc[3] + mr[2*mt+1];
    }
}

__global__ __launch_bounds__(256, 2) void attn_kernel(
    const float* __restrict__ rd, const unsigned char* __restrict__ mask,
    const float* __restrict__ Wc1, const float* __restrict__ bc1,
    const float* __restrict__ Wc2, const float* __restrict__ bc2)
{
    extern __shared__ __align__(16) float sm[];
    float*  k_s = sm + SM_K;
    float*  v_s = sm + SM_V;
    float4* w1  = (float4*)(sm + SM_W1);

    const int b  = blockIdx.y;
    const int q0 = blockIdx.x * QT;
    const int t  = threadIdx.x;
    const unsigned int smem_u32 = (unsigned int)__cvta_generic_to_shared(sm);

    const int wh   = t >> 5;       // warp id: query (cpb) / head (QK, AV)
    const int lane = t & 31;

    // ---- prologue: w1, Wc2 fragments, Q fragments (persistent regs) ----
    if (t < 64)
        w1[t] = make_float4(Wc1[2 * t], Wc1[2 * t + 1], bc1[t], 0.f);

    unsigned bf0[8], bf1[8];
    {
        const int hd = lane >> 2, jc = lane & 3;
#pragma unroll
        for (int s = 0; s < 8; s++) {
            bf0[s] = f2tf(Wc2[hd * 64 + s * 8 + jc]);
            bf1[s] = f2tf(Wc2[hd * 64 + s * 8 + 4 + jc]);
        }
    }
    const float bias0 = bc2[2 * (lane & 3)];
    const float bias1 = bc2[2 * (lane & 3) + 1];

    unsigned qb0[4], qb1[4];
    {
        const int ql = lane >> 2;                 // query index (n-col)
        const bool qv = (q0 + ql) < Qn;
        const float* qrow = &g_q[(size_t)((b * Qn) + (qv ? q0 + ql : 0)) * En + wh * 32];
#pragma unroll
        for (int kst = 0; kst < 4; kst++) {
            float e0 = qv ? qrow[kst * 8 + (lane & 3)]     : 0.f;
            float e1 = qv ? qrow[kst * 8 + 4 + (lane & 3)] : 0.f;
            qb0[kst] = f2tf(e0);
            qb1[kst] = f2tf(e1);
        }
    }
    __syncthreads();

    const int qg_b1 = q0 + wh;
    const size_t rd_row = ((size_t)b * Qn + (qg_b1 < Qn ? qg_b1 : Qn - 1)) * Kn;

    // ldmatrix base address for this lane (K tile)
    const unsigned kbase = smem_u32 +
        (unsigned)((SM_K + (lane & 15) * 260 + wh * 32) * 4) + ((lane >> 4) * 16);
    const int kswz = 8 * ((wh >> 1) & 3);        // cpb/p key swizzle for head wh

    // ---- tile 0: async K/V load overlapped with CPB(0) ----
    {
#pragma unroll
        for (int i = 0; i < 8; i++) {
            int idx = t + i * 256;
            int kk  = idx >> 6, e4 = idx & 63;
            size_t gidx = (size_t)((b * Kn) + kk) * En + e4 * 4;
            cpa16(smem_u32 + (SM_K + kk * 260 + e4 * 4) * 4, &g_k[gidx]);
            cpa16(smem_u32 + (SM_V + kk * 264 + e4 * 4) * 4, &g_v[gidx]);
        }
        CP_COMMIT();
        float dxr[4], dyr[4], mr[4];
#pragma unroll
        for (int g = 0; g < 4; g++) {
            int kr = (lane >> 2) + 8 * g;
            float2 r2 = *(const float2*)&rd[(rd_row + kr) * 2];
            dxr[g] = r2.x; dyr[g] = r2.y;
            mr[g]  = mask[b * Kn + kr] ? MASK_NEG : 0.f;
        }
        cpb_tile(sm + SM_CPB0, w1, bf0, bf1, bias0, bias1, dxr, dyr, mr, lane, wh);
        CP_WAIT0();
        __syncthreads();
    }

    float l_run0 = 0.f, l_run1 = 0.f;      // softmax denom for q = 2(lane&3), +1
    float oc0[4] = {0.f, 0.f, 0.f, 0.f};   // O^T frag, d-tile 0 (dims 0-15 of head)
    float oc1[4] = {0.f, 0.f, 0.f, 0.f};   // d-tile 1 (dims 16-31)

    for (int it = 0; it < NTILES; it++) {
        const int k0 = it * KT;
        float* cpb_cur = sm + ((it & 1) ? SM_CPB1 : SM_CPB0);
        float* cpb_nxt = sm + ((it & 1) ? SM_CPB0 : SM_CPB1);

        // early LDG: rd/mask fragments for next tile
        float dxr[4], dyr[4], mr[4];
        if (it + 1 < NTILES) {
#pragma unroll
            for (int g = 0; g < 4; g++) {
                int kr = k0 + KT + (lane >> 2) + 8 * g;
                float2 r2 = *(const float2*)&rd[(rd_row + kr) * 2];
                dxr[g] = r2.x; dyr[g] = r2.y;
                mr[g]  = mask[b * Kn + kr] ? MASK_NEG : 0.f;
            }
        }

        // ===== B2: QK via tf32 mma + exp (in place into cpb_cur) =====
        {
            float cQK[2][4] = {{0.f,0.f,0.f,0.f},{0.f,0.f,0.f,0.f}};
#pragma unroll
            for (int mt = 0; mt < 2; mt++) {
#pragma unroll
                for (int kst = 0; kst < 4; kst++) {
                    unsigned a0, a1, a2, a3;
                    ldsm4(a0, a1, a2, a3, kbase + mt * (16 * 260 * 4) + kst * 32);
                    mma_tf32(cQK[mt], a0, a1, a2, a3, qb0[kst], qb1[kst]);
                }
            }
            const int qc = 2 * (lane & 3);
            float l0t = 0.f, l1t = 0.f;
#pragma unroll
            for (int mt = 0; mt < 2; mt++) {
                int key0 = (lane >> 2) + 16 * mt;
                int key1 = key0 + 8;
                int r0 = (wh * 8 + qc) * 36;
                int r1 = (wh * 8 + qc + 1) * 36;
                float p0 = __expf(cQK[mt][0] + cpb_cur[r0 + (key0 ^ kswz)]);
                float p1 = __expf(cQK[mt][1] + cpb_cur[r1 + (key0 ^ kswz)]);
                float p2 = __expf(cQK[mt][2] + cpb_cur[r0 + (key1 ^ kswz)]);
                float p3 = __expf(cQK[mt][3] + cpb_cur[r1 + (key1 ^ kswz)]);
                cpb_cur[r0 + (key0 ^ kswz)] = p0;
                cpb_cur[r1 + (key0 ^ kswz)] = p1;
                cpb_cur[r0 + (key1 ^ kswz)] = p2;
                cpb_cur[r1 + (key1 ^ kswz)] = p3;
                l0t += p0 + p2;
                l1t += p1 + p3;
            }
#pragma unroll
            for (int off = 4; off < 32; off <<= 1) {
                l0t += __shfl_xor_sync(0xffffffffu, l0t, off);
                l1t += __shfl_xor_sync(0xffffffffu, l1t, off);
            }
            l_run0 += l0t;
            l_run1 += l1t;
        }
        CP_WAIT0();           // V(it) landed
        __syncthreads();      // k_s free; v_s visible; (p is warp-local)

        // issue K(it+1)
        if (it + 1 < NTILES) {
#pragma unroll
            for (int i = 0; i < 8; i++) {
                int idx = t + i * 256;
                int kk  = idx >> 6, e4 = idx & 63;
                size_t gidx = (size_t)((b * Kn) + (k0 + KT + kk)) * En + e4 * 4;
                cpa16(smem_u32 + (SM_K + kk * 260 + e4 * 4) * 4, &g_k[gidx]);
            }
            CP_COMMIT();
        }

        // ===== C: AV via tf32 mma (O^T += V^T p^T), warp-local p =====
        {
            unsigned pb0[4], pb1[4];
            const int prow = (wh * 8 + (lane >> 2)) * 36;   // q = lane>>2
#pragma unroll
            for (int kst = 0; kst < 4; kst++) {
                pb0[kst] = f2tf(cpb_cur[prow + ((kst * 8 + (lane & 3)) ^ kswz)]);
                pb1[kst] = f2tf(cpb_cur[prow + ((kst * 8 + 4 + (lane & 3)) ^ kswz)]);
            }
            const float* vb = &v_s[wh * 32];
#pragma unroll
            for (int dmt = 0; dmt < 2; dmt++) {
                float* oc = dmt ? oc1 : oc0;
                int d0 = (lane >> 2) + 16 * dmt;
                int d1 = d0 + 8;
#pragma unroll
                for (int kst = 0; kst < 4; kst++) {
                    int ka = kst * 8 + (lane & 3);
                    int kb = ka + 4;
                    unsigned a0 = f2tf(vb[ka * 264 + d0]);
                    unsigned a1 = f2tf(vb[ka * 264 + d1]);
                    unsigned a2 = f2tf(vb[kb * 264 + d0]);
                    unsigned a3 = f2tf(vb[kb * 264 + d1]);
                    mma_tf32(oc, a0, a1, a2, a3, pb0[kst], pb1[kst]);
                }
            }
        }

        // ===== CPB(it+1) into cpb_nxt =====
        if (it + 1 < NTILES)
            cpb_tile(cpb_nxt, w1, bf0, bf1, bias0, bias1, dxr, dyr, mr, lane, wh);

        __syncthreads();      // v_s free

        if (it + 1 < NTILES) {
#pragma unroll
            for (int i = 0; i < 8; i++) {
                int idx = t + i * 256;
                int kk  = idx >> 6, e4 = idx & 63;
                size_t gidx = (size_t)((b * Kn) + (k0 + KT + kk)) * En + e4 * 4;
                cpa16(smem_u32 + (SM_V + kk * 264 + e4 * 4) * 4, &g_v[gidx]);
            }
            CP_COMMIT();
            CP_WAIT1();        // K(it+1) landed; V(it+1) still in flight
            __syncthreads();   // k_s + cpb_nxt visible for next B2
        }
    }

    // ---- epilogue: O^T frag (d = lane>>2 (+8) + 16*dmt, q = 2(lane&3) (+1)) ----
    {
        const int qc = 2 * (lane & 3);
        const float inv0 = 1.f / l_run0;
        const float inv1 = 1.f / l_run1;
        float* base0 = &g_att[(size_t)((b * Qn) + (q0 + qc)) * En + wh * 32];
        float* base1 = base0 + En;                 // q = qc+1
#pragma unroll
        for (int dmt = 0; dmt < 2; dmt++) {
            float* oc = dmt ? oc1 : oc0;
            int d0 = (lane >> 2) + 16 * dmt;
            if (q0 + qc < Qn) {
                base0[d0]     = oc[0] * inv0;
                base0[d0 + 8] = oc[2] * inv0;
            }
            if (q0 + qc + 1 < Qn) {
                base1[d0]     = oc[1] * inv1;
                base1[d0 + 8] = oc[3] * inv1;
            }
        }
    }
}

// ---------------- launch ----------------
extern "C" void kernel_launch(void* const* d_in, const int* in_sizes, int n_in,
                              void* d_out, int out_size)
{
    const float*         nodes  = (const float*)d_in[0];
    const float*         images = (const float*)d_in[1];
    const unsigned char* imask  = (const unsigned char*)d_in[2];
    const float*         rd     = (const float*)d_in[3];
    const float*         Wq     = (const float*)d_in[4];
    const float*         bq     = (const float*)d_in[5];
    const float*         Wkv    = (const float*)d_in[6];
    const float*         bkv    = (const float*)d_in[7];
    const float*         Wc1    = (const float*)d_in[8];
    const float*         bc1    = (const float*)d_in[9];
    const float*         Wc2    = (const float*)d_in[10];
    const float*         bc2    = (const float*)d_in[11];
    const float*         Wo     = (const float*)d_in[12];
    const float*         bo     = (const float*)d_in[13];
    float*               out    = (float*)d_out;

    float *pq, *pk, *pv, *pa;
    cudaGetSymbolAddress((void**)&pq, g_q);
    cudaGetSymbolAddress((void**)&pk, g_k);
    cudaGetSymbolAddress((void**)&pv, g_v);
    cudaGetSymbolAddress((void**)&pa, g_att);

    const int MQ = Bn * Qn;   // 3600
    const int MK = Bn * Kn;   // 4096

    {
        dim3 g((MQ + 63) / 64, 4);
        proj_gemm<<<g, 256>>>(nodes, Wq, bq, pq, MQ, SCALE_Q);
    }
    {
        dim3 g((MK + 63) / 64, 4);
        proj_gemm<<<g, 256>>>(images, Wkv,             bkv,       pk, MK, 1.f);
        proj_gemm<<<g, 256>>>(images, Wkv + 256 * 256, bkv + 256, pv, MK, 1.f);
    }
    {
        cudaFuncSetAttribute(attn_kernel,
                             cudaFuncAttributeMaxDynamicSharedMemorySize, SM_BYTES);
        dim3 g((Qn + QT - 1) / QT, Bn);   // (113, 4) = 452 CTAs
        attn_kernel<<<g, 256, SM_BYTES>>>(rd, imask, Wc1, bc1, Wc2, bc2);
    }
    {
        dim3 g((MQ + 63) / 64, 4);
        proj_gemm<<<g, 256>>>(pa, Wo, bo, out, MQ, 1.f);
    }
}

// round 10
// speedup vs baseline: 3.4618x; 1.1147x over previous
#include <cuda_runtime.h>
#include <cuda_bf16.h>
#include <math.h>

// ---------------- problem constants ----------------
#define Bn 4
#define Qn 900
#define Kn 1024
#define En 256
#define Hn 8
#define Dn 32
#define QT 8
#define KT 32
#define NTILES (Kn / KT)
#define SCALE_Q 0.17677669529663687f  // 1/sqrt(32)
#define MASK_NEG (-10000.0f)

typedef unsigned long long ull;

// ---------------- f32x2 packed helpers (proj gemm) ----------------
__device__ __forceinline__ ull pk2(float lo, float hi) {
    ull r; asm("mov.b64 %0, {%1,%2};" : "=l"(r) : "f"(lo), "f"(hi)); return r;
}
__device__ __forceinline__ void upk2(ull v, float& lo, float& hi) {
    asm("mov.b64 {%0,%1}, %2;" : "=f"(lo), "=f"(hi) : "l"(v));
}
__device__ __forceinline__ ull fma2(ull a, ull b, ull c) {
    ull r; asm("fma.rn.f32x2 %0, %1, %2, %3;" : "=l"(r) : "l"(a), "l"(b), "l"(c)); return r;
}

// ---------------- tf32 mma helpers ----------------
__device__ __forceinline__ unsigned f2tf(float f) {
    unsigned r; asm("cvt.rna.tf32.f32 %0, %1;" : "=r"(r) : "f"(f)); return r;
}
__device__ __forceinline__ void mma_tf32(float c[4],
    unsigned a0, unsigned a1, unsigned a2, unsigned a3,
    unsigned b0, unsigned b1)
{
    asm volatile(
        "mma.sync.aligned.m16n8k8.row.col.f32.tf32.tf32.f32 "
        "{%0,%1,%2,%3}, {%4,%5,%6,%7}, {%8,%9}, {%0,%1,%2,%3};"
        : "+f"(c[0]), "+f"(c[1]), "+f"(c[2]), "+f"(c[3])
        : "r"(a0), "r"(a1), "r"(a2), "r"(a3), "r"(b0), "r"(b1));
}
__device__ __forceinline__ void ldsm4(unsigned& r0, unsigned& r1,
                                      unsigned& r2, unsigned& r3, unsigned addr)
{
    asm volatile("ldmatrix.sync.aligned.m8n8.x4.shared.b16 {%0,%1,%2,%3}, [%4];"
                 : "=r"(r0), "=r"(r1), "=r"(r2), "=r"(r3) : "r"(addr));
}

// ---------------- cp.async helpers ----------------
__device__ __forceinline__ void cpa16(unsigned int dst, const void* src) {
    asm volatile("cp.async.cg.shared.global [%0], [%1], 16;" :: "r"(dst), "l"(src));
}
#define CP_COMMIT() asm volatile("cp.async.commit_group;")
#define CP_WAIT0()  asm volatile("cp.async.wait_group 0;" ::: "memory")
#define CP_WAIT1()  asm volatile("cp.async.wait_group 1;" ::: "memory")

// ---------------- scratch ----------------
__device__ __align__(16) float g_q[Bn * Qn * En];
__device__ __align__(16) float g_k[Bn * Kn * En];
__device__ __align__(16) float g_v[Bn * Kn * En];
__device__ __align__(16) float g_att[Bn * Qn * En];

// ---------------- projection GEMM body (register-prefetch pipelined) ----------------
__device__ __forceinline__ void proj_body(
    float (*As)[64], float (*Bs)[64],
    const float* __restrict__ A, const float* __restrict__ W,
    const float* __restrict__ bias, float* __restrict__ C,
    int M, float scale)
{
    const int m0 = blockIdx.x * 64;
    if (m0 >= M) return;
    const int n0 = blockIdx.y * 64;
    const int t  = threadIdx.x;
    const int tx = t & 15;
    const int ty = t >> 4;
    const int lr = t >> 2;
    const int lc = (t & 3) * 4;

    ull acc2[4][2];
#pragma unroll
    for (int i = 0; i < 4; i++) { acc2[i][0] = 0ULL; acc2[i][1] = 0ULL; }

    const bool arow_ok = (m0 + lr) < M;
    float4 a_pre = make_float4(0.f, 0.f, 0.f, 0.f);
    if (arow_ok) a_pre = *(const float4*)&A[(size_t)(m0 + lr) * 256 + lc];
    float4 b_pre = *(const float4*)&W[(size_t)(n0 + lr) * 256 + lc];

    for (int k0 = 0; k0 < 256; k0 += 16) {
        As[lc + 0][lr] = a_pre.x; As[lc + 1][lr] = a_pre.y;
        As[lc + 2][lr] = a_pre.z; As[lc + 3][lr] = a_pre.w;
        Bs[lc + 0][lr] = b_pre.x; Bs[lc + 1][lr] = b_pre.y;
        Bs[lc + 2][lr] = b_pre.z; Bs[lc + 3][lr] = b_pre.w;
        __syncthreads();

        // prefetch next chunk — LDG latency hides behind compute below
        if (k0 < 240) {
            if (arow_ok)
                a_pre = *(const float4*)&A[(size_t)(m0 + lr) * 256 + k0 + 16 + lc];
            else
                a_pre = make_float4(0.f, 0.f, 0.f, 0.f);
            b_pre = *(const float4*)&W[(size_t)(n0 + lr) * 256 + k0 + 16 + lc];
        }

#pragma unroll
        for (int kk = 0; kk < 16; kk++) {
            float4 av = *(const float4*)&As[kk][ty * 4];
            float4 bv = *(const float4*)&Bs[kk][tx * 4];
            ull b01 = pk2(bv.x, bv.y);
            ull b23 = pk2(bv.z, bv.w);
            float am[4] = {av.x, av.y, av.z, av.w};
#pragma unroll
            for (int i = 0; i < 4; i++) {
                ull ad = pk2(am[i], am[i]);
                acc2[i][0] = fma2(b01, ad, acc2[i][0]);
                acc2[i][1] = fma2(b23, ad, acc2[i][1]);
            }
        }
        __syncthreads();
    }

#pragma unroll
    for (int i = 0; i < 4; i++) {
        int m = m0 + ty * 4 + i;
        if (m < M) {
            int n = n0 + tx * 4;
            float c0, c1, c2, c3;
            upk2(acc2[i][0], c0, c1);
            upk2(acc2[i][1], c2, c3);
            float4 o;
            o.x = scale * (c0 + bias[n + 0]);
            o.y = scale * (c1 + bias[n + 1]);
            o.z = scale * (c2 + bias[n + 2]);
            o.w = scale * (c3 + bias[n + 3]);
            *(float4*)&C[(size_t)m * 256 + n] = o;
        }
    }
}

// fused q/k/v projections: blockIdx.z selects which GEMM
__global__ __launch_bounds__(256) void proj3_kernel(
    const float* __restrict__ nodes, const float* __restrict__ images,
    const float* __restrict__ Wq,  const float* __restrict__ bq,
    const float* __restrict__ Wkv, const float* __restrict__ bkv,
    float* __restrict__ pq, float* __restrict__ pk, float* __restrict__ pv)
{
    __shared__ __align__(16) float As[16][64];
    __shared__ __align__(16) float Bs[16][64];
    if (blockIdx.z == 0)
        proj_body(As, Bs, nodes,  Wq,              bq,        pq, Bn * Qn, SCALE_Q);
    else if (blockIdx.z == 1)
        proj_body(As, Bs, images, Wkv,             bkv,       pk, Bn * Kn, 1.f);
    else
        proj_body(As, Bs, images, Wkv + 256 * 256, bkv + 256, pv, Bn * Kn, 1.f);
}

__global__ __launch_bounds__(256) void projo_kernel(
    const float* __restrict__ A, const float* __restrict__ W,
    const float* __restrict__ bias, float* __restrict__ C, int M)
{
    __shared__ __align__(16) float As[16][64];
    __shared__ __align__(16) float Bs[16][64];
    proj_body(As, Bs, A, W, bias, C, M, 1.f);
}

// ---------------- fused attention (full tensor-core) ----------------
// SMEM (float offsets)
#define SM_K     0        // [32][260]   8320  (ldmatrix rows; 16B bank rotation)
#define SM_V     8320     // [32][264]   8448  (scalar A-frag loads; 8*key+d bijection)
#define SM_CPB0  16768    // [64][36]    2304  rows = h*8+q, key XOR-swizzled by 8*((h>>1)&3)
#define SM_CPB1  19072    // [64][36]    2304
#define SM_W1    21376    // float4[64]  (wx,wy,b,0)  256
#define SM_FLOATS 21632
#define SM_BYTES (SM_FLOATS * 4)

// CPB layer-2 via tf32 mma. warp = query wq; A = hidden[32 keys x 64], B = Wc2^T (regs).
__device__ __forceinline__ void cpb_tile(
    float* __restrict__ dst, const float4* __restrict__ w1,
    const unsigned* __restrict__ bf0, const unsigned* __restrict__ bf1,
    float bias0, float bias1,
    const float* dxr, const float* dyr, const float* mr, int lane, int wq)
{
    float c0[4], c1[4];
    c0[0] = c0[2] = bias0; c0[1] = c0[3] = bias1;
    c1[0] = c1[2] = bias0; c1[1] = c1[3] = bias1;
#pragma unroll
    for (int s = 0; s < 8; s++) {
        float4 wA = w1[s * 8 + (lane & 3)];
        float4 wB = w1[s * 8 + 4 + (lane & 3)];
        unsigned b0 = bf0[s], b1 = bf1[s];
#pragma unroll
        for (int mt = 0; mt < 2; mt++) {
            float h00 = fmaxf(fmaf(wA.x, dxr[2*mt],   fmaf(wA.y, dyr[2*mt],   wA.z)), 0.f);
            float h10 = fmaxf(fmaf(wA.x, dxr[2*mt+1], fmaf(wA.y, dyr[2*mt+1], wA.z)), 0.f);
            float h01 = fmaxf(fmaf(wB.x, dxr[2*mt],   fmaf(wB.y, dyr[2*mt],   wB.z)), 0.f);
            float h11 = fmaxf(fmaf(wB.x, dxr[2*mt+1], fmaf(wB.y, dyr[2*mt+1], wB.z)), 0.f);
            float* cc = mt ? c1 : c0;
            mma_tf32(cc, __float_as_uint(h00), __float_as_uint(h10),
                         __float_as_uint(h01), __float_as_uint(h11), b0, b1);
        }
    }
    const int kswz = 8 * (lane & 3);           // = 8*((h>>1)&3) for h = 2(lane&3)+j
    const int h0 = 2 * (lane & 3), h1 = h0 + 1;
#pragma unroll
    for (int mt = 0; mt < 2; mt++) {
        float* cc = mt ? c1 : c0;
        int key0 = (lane >> 2) + 16 * mt;
        int key1 = key0 + 8;
        dst[(h0 * 8 + wq) * 36 + (key0 ^ kswz)] = cc[0] + mr[2*mt];
        dst[(h1 * 8 + wq) * 36 + (key0 ^ kswz)] = cc[1] + mr[2*mt];
        dst[(h0 * 8 + wq) * 36 + (key1 ^ kswz)] = cc[2] + mr[2*mt+1];
        dst[(h1 * 8 + wq) * 36 + (key1 ^ kswz)] = cc[3] + mr[2*mt+1];
    }
}

__global__ __launch_bounds__(256, 2) void attn_kernel(
    const float* __restrict__ rd, const unsigned char* __restrict__ mask,
    const float* __restrict__ Wc1, const float* __restrict__ bc1,
    const float* __restrict__ Wc2, const float* __restrict__ bc2)
{
    extern __shared__ __align__(16) float sm[];
    float*  k_s = sm + SM_K;
    float*  v_s = sm + SM_V;
    float4* w1  = (float4*)(sm + SM_W1);

    const int b  = blockIdx.y;
    const int q0 = blockIdx.x * QT;
    const int t  = threadIdx.x;
    const unsigned int smem_u32 = (unsigned int)__cvta_generic_to_shared(sm);

    const int wh   = t >> 5;       // warp id: query (cpb) / head (QK, AV)
    const int lane = t & 31;

    // ---- prologue: w1, Wc2 fragments, Q fragments (persistent regs) ----
    if (t < 64)
        w1[t] = make_float4(Wc1[2 * t], Wc1[2 * t + 1], bc1[t], 0.f);

    unsigned bf0[8], bf1[8];
    {
        const int hd = lane >> 2, jc = lane & 3;
#pragma unroll
        for (int s = 0; s < 8; s++) {
            bf0[s] = f2tf(Wc2[hd * 64 + s * 8 + jc]);
            bf1[s] = f2tf(Wc2[hd * 64 + s * 8 + 4 + jc]);
        }
    }
    const float bias0 = bc2[2 * (lane & 3)];
    const float bias1 = bc2[2 * (lane & 3) + 1];

    unsigned qb0[4], qb1[4];
    {
        const int ql = lane >> 2;                 // query index (n-col)
        const bool qv = (q0 + ql) < Qn;
        const float* qrow = &g_q[(size_t)((b * Qn) + (qv ? q0 + ql : 0)) * En + wh * 32];
#pragma unroll
        for (int kst = 0; kst < 4; kst++) {
            float e0 = qv ? qrow[kst * 8 + (lane & 3)]     : 0.f;
            float e1 = qv ? qrow[kst * 8 + 4 + (lane & 3)] : 0.f;
            qb0[kst] = f2tf(e0);
            qb1[kst] = f2tf(e1);
        }
    }
    __syncthreads();

    const int qg_b1 = q0 + wh;
    const size_t rd_row = ((size_t)b * Qn + (qg_b1 < Qn ? qg_b1 : Qn - 1)) * Kn;

    // ldmatrix base address for this lane (K tile)
    const unsigned kbase = smem_u32 +
        (unsigned)((SM_K + (lane & 15) * 260 + wh * 32) * 4) + ((lane >> 4) * 16);
    const int kswz = 8 * ((wh >> 1) & 3);        // cpb/p key swizzle for head wh

    // ---- tile 0: async K/V load overlapped with CPB(0) ----
    {
#pragma unroll
        for (int i = 0; i < 8; i++) {
            int idx = t + i * 256;
            int kk  = idx >> 6, e4 = idx & 63;
            size_t gidx = (size_t)((b * Kn) + kk) * En + e4 * 4;
            cpa16(smem_u32 + (SM_K + kk * 260 + e4 * 4) * 4, &g_k[gidx]);
            cpa16(smem_u32 + (SM_V + kk * 264 + e4 * 4) * 4, &g_v[gidx]);
        }
        CP_COMMIT();
        float dxr[4], dyr[4], mr[4];
#pragma unroll
        for (int g = 0; g < 4; g++) {
            int kr = (lane >> 2) + 8 * g;
            float2 r2 = *(const float2*)&rd[(rd_row + kr) * 2];
            dxr[g] = r2.x; dyr[g] = r2.y;
            mr[g]  = mask[b * Kn + kr] ? MASK_NEG : 0.f;
        }
        cpb_tile(sm + SM_CPB0, w1, bf0, bf1, bias0, bias1, dxr, dyr, mr, lane, wh);
        CP_WAIT0();
        __syncthreads();
    }

    float l_run0 = 0.f, l_run1 = 0.f;      // per-lane partial softmax denominators
    float oc0[4] = {0.f, 0.f, 0.f, 0.f};   // O^T frag, d-tile 0 (dims 0-15 of head)
    float oc1[4] = {0.f, 0.f, 0.f, 0.f};   // d-tile 1 (dims 16-31)

    for (int it = 0; it < NTILES; it++) {
        const int k0 = it * KT;
        float* cpb_cur = sm + ((it & 1) ? SM_CPB1 : SM_CPB0);
        float* cpb_nxt = sm + ((it & 1) ? SM_CPB0 : SM_CPB1);

        // early LDG: rd/mask fragments for next tile
        float dxr[4], dyr[4], mr[4];
        if (it + 1 < NTILES) {
#pragma unroll
            for (int g = 0; g < 4; g++) {
                int kr = k0 + KT + (lane >> 2) + 8 * g;
                float2 r2 = *(const float2*)&rd[(rd_row + kr) * 2];
                dxr[g] = r2.x; dyr[g] = r2.y;
                mr[g]  = mask[b * Kn + kr] ? MASK_NEG : 0.f;
            }
        }

        // ===== B2: QK via tf32 mma + exp (in place into cpb_cur) =====
        {
            float cQK[2][4] = {{0.f,0.f,0.f,0.f},{0.f,0.f,0.f,0.f}};
#pragma unroll
            for (int mt = 0; mt < 2; mt++) {
#pragma unroll
                for (int kst = 0; kst < 4; kst++) {
                    unsigned a0, a1, a2, a3;
                    ldsm4(a0, a1, a2, a3, kbase + mt * (16 * 260 * 4) + kst * 32);
                    mma_tf32(cQK[mt], a0, a1, a2, a3, qb0[kst], qb1[kst]);
                }
            }
            const int qc = 2 * (lane & 3);
#pragma unroll
            for (int mt = 0; mt < 2; mt++) {
                int key0 = (lane >> 2) + 16 * mt;
                int key1 = key0 + 8;
                int r0 = (wh * 8 + qc) * 36;
                int r1 = (wh * 8 + qc + 1) * 36;
                float p0 = __expf(cQK[mt][0] + cpb_cur[r0 + (key0 ^ kswz)]);
                float p1 = __expf(cQK[mt][1] + cpb_cur[r1 + (key0 ^ kswz)]);
                float p2 = __expf(cQK[mt][2] + cpb_cur[r0 + (key1 ^ kswz)]);
                float p3 = __expf(cQK[mt][3] + cpb_cur[r1 + (key1 ^ kswz)]);
                cpb_cur[r0 + (key0 ^ kswz)] = p0;
                cpb_cur[r1 + (key0 ^ kswz)] = p1;
                cpb_cur[r0 + (key1 ^ kswz)] = p2;
                cpb_cur[r1 + (key1 ^ kswz)] = p3;
                l_run0 += p0 + p2;          // lane-partial; reduced in epilogue
                l_run1 += p1 + p3;
            }
        }
        CP_WAIT0();           // V(it) landed
        __syncthreads();      // k_s free; v_s visible; (p is warp-local)

        // issue K(it+1)
        if (it + 1 < NTILES) {
#pragma unroll
            for (int i = 0; i < 8; i++) {
                int idx = t + i * 256;
                int kk  = idx >> 6, e4 = idx & 63;
                size_t gidx = (size_t)((b * Kn) + (k0 + KT + kk)) * En + e4 * 4;
                cpa16(smem_u32 + (SM_K + kk * 260 + e4 * 4) * 4, &g_k[gidx]);
            }
            CP_COMMIT();
        }

        // ===== C: AV via tf32 mma (O^T += V^T p^T), warp-local p, raw-bit tf32 =====
        {
            unsigned pb0[4], pb1[4];
            const int prow = (wh * 8 + (lane >> 2)) * 36;   // q = lane>>2
#pragma unroll
            for (int kst = 0; kst < 4; kst++) {
                pb0[kst] = __float_as_uint(cpb_cur[prow + ((kst * 8 + (lane & 3)) ^ kswz)]);
                pb1[kst] = __float_as_uint(cpb_cur[prow + ((kst * 8 + 4 + (lane & 3)) ^ kswz)]);
            }
            const float* vb = &v_s[wh * 32];
#pragma unroll
            for (int dmt = 0; dmt < 2; dmt++) {
                float* oc = dmt ? oc1 : oc0;
                int d0 = (lane >> 2) + 16 * dmt;
                int d1 = d0 + 8;
#pragma unroll
                for (int kst = 0; kst < 4; kst++) {
                    int ka = kst * 8 + (lane & 3);
                    int kb = ka + 4;
                    unsigned a0 = __float_as_uint(vb[ka * 264 + d0]);
                    unsigned a1 = __float_as_uint(vb[ka * 264 + d1]);
                    unsigned a2 = __float_as_uint(vb[kb * 264 + d0]);
                    unsigned a3 = __float_as_uint(vb[kb * 264 + d1]);
                    mma_tf32(oc, a0, a1, a2, a3, pb0[kst], pb1[kst]);
                }
            }
        }

        // ===== CPB(it+1) into cpb_nxt =====
        if (it + 1 < NTILES)
            cpb_tile(cpb_nxt, w1, bf0, bf1, bias0, bias1, dxr, dyr, mr, lane, wh);

        __syncthreads();      // v_s free

        if (it + 1 < NTILES) {
#pragma unroll
            for (int i = 0; i < 8; i++) {
                int idx = t + i * 256;
                int kk  = idx >> 6, e4 = idx & 63;
                size_t gidx = (size_t)((b * Kn) + (k0 + KT + kk)) * En + e4 * 4;
                cpa16(smem_u32 + (SM_V + kk * 264 + e4 * 4) * 4, &g_v[gidx]);
            }
            CP_COMMIT();
            CP_WAIT1();        // K(it+1) landed; V(it+1) still in flight
            __syncthreads();   // k_s + cpb_nxt visible for next B2
        }
    }

    // ---- epilogue: reduce l over key-lanes, then store O^T fragment ----
    {
#pragma unroll
        for (int off = 4; off < 32; off <<= 1) {
            l_run0 += __shfl_xor_sync(0xffffffffu, l_run0, off);
            l_run1 += __shfl_xor_sync(0xffffffffu, l_run1, off);
        }
        const int qc = 2 * (lane & 3);
        const float inv0 = 1.f / l_run0;
        const float inv1 = 1.f / l_run1;
        float* base0 = &g_att[(size_t)((b * Qn) + (q0 + qc)) * En + wh * 32];
        float* base1 = base0 + En;                 // q = qc+1
#pragma unroll
        for (int dmt = 0; dmt < 2; dmt++) {
            float* oc = dmt ? oc1 : oc0;
            int d0 = (lane >> 2) + 16 * dmt;
            if (q0 + qc < Qn) {
                base0[d0]     = oc[0] * inv0;
                base0[d0 + 8] = oc[2] * inv0;
            }
            if (q0 + qc + 1 < Qn) {
                base1[d0]     = oc[1] * inv1;
                base1[d0 + 8] = oc[3] * inv1;
            }
        }
    }
}

// ---------------- launch ----------------
extern "C" void kernel_launch(void* const* d_in, const int* in_sizes, int n_in,
                              void* d_out, int out_size)
{
    const float*         nodes  = (const float*)d_in[0];
    const float*         images = (const float*)d_in[1];
    const unsigned char* imask  = (const unsigned char*)d_in[2];
    const float*         rd     = (const float*)d_in[3];
    const float*         Wq     = (const float*)d_in[4];
    const float*         bq     = (const float*)d_in[5];
    const float*         Wkv    = (const float*)d_in[6];
    const float*         bkv    = (const float*)d_in[7];
    const float*         Wc1    = (const float*)d_in[8];
    const float*         bc1    = (const float*)d_in[9];
    const float*         Wc2    = (const float*)d_in[10];
    const float*         bc2    = (const float*)d_in[11];
    const float*         Wo     = (const float*)d_in[12];
    const float*         bo     = (const float*)d_in[13];
    float*               out    = (float*)d_out;

    float *pq, *pk, *pv, *pa;
    cudaGetSymbolAddress((void**)&pq, g_q);
    cudaGetSymbolAddress((void**)&pk, g_k);
    cudaGetSymbolAddress((void**)&pv, g_v);
    cudaGetSymbolAddress((void**)&pa, g_att);

    const int MQ = Bn * Qn;   // 3600

    // fused q/k/v projections (one launch)
    {
        dim3 g(64, 4, 3);     // x covers max M=4096 rows; q-blocks past 3600 exit early
        proj3_kernel<<<g, 256>>>(nodes, images, Wq, bq, Wkv, bkv, pq, pk, pv);
    }
    // fused attention
    {
        cudaFuncSetAttribute(attn_kernel,
                             cudaFuncAttributeMaxDynamicSharedMemorySize, SM_BYTES);
        dim3 g((Qn + QT - 1) / QT, Bn);   // (113, 4) = 452 CTAs
        attn_kernel<<<g, 256, SM_BYTES>>>(rd, imask, Wc1, bc1, Wc2, bc2);
    }
    // output projection
    {
        dim3 g((MQ + 63) / 64, 4);
        projo_kernel<<<g, 256>>>(pa, Wo, bo, out, MQ);
    }
}